// round 7
// baseline (speedup 1.0000x reference)
#include <cuda_runtime.h>
#include <math.h>
#include <stdint.h>

// ---------------------------------------------------------------------------
// Shapes: x (N=2, T=2048, C=512), H=8, hd=64, WIN=63, LEFT=31, hid=2048
// ---------------------------------------------------------------------------
#define C_DIM   512
#define HID_DIM 2048
#define QKV_DIM 1536
#define HEAD_D  64
#define WIN     63
#define LEFT    31
#define M_ROWS  4096

#define PAD 20

// attention tiling
#define ATT_TT   64
#define ATT_SPAN (ATT_TT + WIN - 1) // 126
#define ATT_LD   65

// ---------------------------------------------------------------------------
// Scratch
// ---------------------------------------------------------------------------
__device__ float g_h   [M_ROWS * C_DIM];
__device__ float g_qkv [M_ROWS * QKV_DIM];
__device__ float g_att [M_ROWS * C_DIM];
__device__ float g_x2  [M_ROWS * C_DIM];
__device__ float g_m1  [M_ROWS * HID_DIM];
__device__ float g_part[2 * M_ROWS * C_DIM];

// ---------------------------------------------------------------------------
// PTX helpers
// ---------------------------------------------------------------------------
__device__ __forceinline__ void cp_async16(void* smem, const void* gmem) {
    uint32_t s = (uint32_t)__cvta_generic_to_shared(smem);
    asm volatile("cp.async.cg.shared.global [%0], [%1], 16;\n" :: "r"(s), "l"(gmem));
}
__device__ __forceinline__ void mma_tf32(float* c, const uint32_t* a, const uint32_t* b) {
    asm volatile(
        "mma.sync.aligned.m16n8k8.row.col.f32.tf32.tf32.f32 "
        "{%0,%1,%2,%3}, {%4,%5,%6,%7}, {%8,%9}, {%0,%1,%2,%3};\n"
        : "+f"(c[0]), "+f"(c[1]), "+f"(c[2]), "+f"(c[3])
        : "r"(a[0]), "r"(a[1]), "r"(a[2]), "r"(a[3]), "r"(b[0]), "r"(b[1]));
}

// ---------------------------------------------------------------------------
// LayerNorm (standalone, used for LN1)
// ---------------------------------------------------------------------------
__global__ __launch_bounds__(128) void ln_kernel(
    const float* __restrict__ x, const float* __restrict__ w,
    const float* __restrict__ b, float* __restrict__ out)
{
    int row = blockIdx.x;
    int tid = threadIdx.x;
    const float4* xr = (const float4*)(x + (size_t)row * C_DIM);
    float4 v = xr[tid];
    float s  = v.x + v.y + v.z + v.w;
    float sq = v.x*v.x + v.y*v.y + v.z*v.z + v.w*v.w;
    #pragma unroll
    for (int o = 16; o > 0; o >>= 1) {
        s  += __shfl_xor_sync(0xffffffffu, s,  o);
        sq += __shfl_xor_sync(0xffffffffu, sq, o);
    }
    __shared__ float ss[4], ssq[4];
    if ((tid & 31) == 0) { ss[tid >> 5] = s; ssq[tid >> 5] = sq; }
    __syncthreads();
    s  = ss[0]  + ss[1]  + ss[2]  + ss[3];
    sq = ssq[0] + ssq[1] + ssq[2] + ssq[3];
    float mu  = s * (1.0f / C_DIM);
    float var = sq * (1.0f / C_DIM) - mu * mu;
    float inv = rsqrtf(var + 1e-5f);
    float4 wv = ((const float4*)w)[tid];
    float4 bv = ((const float4*)b)[tid];
    float4 o;
    o.x = (v.x - mu) * inv * wv.x + bv.x;
    o.y = (v.y - mu) * inv * wv.y + bv.y;
    o.z = (v.z - mu) * inv * wv.z + bv.z;
    o.w = (v.w - mu) * inv * wv.w + bv.w;
    ((float4*)(out + (size_t)row * C_DIM))[tid] = o;
}

// ---------------------------------------------------------------------------
// Unified TF32 pipelined GEMM.  C[M,N] = A[M,K(slice)] @ B^T + epilogue
// BM=64, BN=128, BK=16, 3-stage cp.async, one sync per chunk, (256,3).
// SPLITK>1: raw partials to part buffer (z = blockIdx.z slice of K).
// ---------------------------------------------------------------------------
template<int SPLITK, bool RES, bool GELU>
__global__ __launch_bounds__(256, 3) void tc_gemm_pipe(
    const float* __restrict__ A, const float* __restrict__ B,
    const float* __restrict__ bias, const float* __restrict__ res,
    float* __restrict__ Cout, int M, int N, int K)
{
    constexpr int BM = 64, BN = 128, BK = 16, ST = 3;
    constexpr int MT = 2;

    __shared__ __align__(16) float smA[ST][BM * PAD];
    __shared__ __align__(16) float smB[ST][BN * PAD];

    const int tid    = threadIdx.x;
    const int wid    = tid >> 5;
    const int lane   = tid & 31;
    const int g      = lane >> 2;
    const int tg     = lane & 3;
    const int warp_m = wid & 1;
    const int warp_n = wid >> 1;

    const int Kl = K / SPLITK;
    const int z  = (SPLITK > 1) ? blockIdx.z : 0;

    const float* Ab = A + (size_t)blockIdx.y * BM * K + (size_t)z * Kl;
    const float* Bb = B + (size_t)blockIdx.x * BN * K + (size_t)z * Kl;

    float acc[MT][4][4];
    #pragma unroll
    for (int mt = 0; mt < MT; mt++)
        #pragma unroll
        for (int nt = 0; nt < 4; nt++)
            #pragma unroll
            for (int i = 0; i < 4; i++) acc[mt][nt][i] = 0.0f;

    const int arow = tid >> 2;
    const int aq   = (tid & 3) << 2;
    auto load_chunk = [&](int buf, int k0) {
        cp_async16(&smA[buf][arow * PAD + aq], Ab + (size_t)arow * K + k0 + aq);
        #pragma unroll
        for (int it = 0; it < 2; ++it) {
            int i = tid + it * 256;
            int r = i >> 2;
            int q = (i & 3) << 2;
            cp_async16(&smB[buf][r * PAD + q], Bb + (size_t)r * K + k0 + q);
        }
    };

    const int nch = Kl / BK;
    load_chunk(0, 0);
    asm volatile("cp.async.commit_group;");
    load_chunk(1, BK);
    asm volatile("cp.async.commit_group;");

    for (int c = 0; c < nch; ++c) {
        asm volatile("cp.async.wait_group 1;");
        __syncthreads();

        if (c + 2 < nch) load_chunk((c + 2) % ST, (c + 2) * BK);
        asm volatile("cp.async.commit_group;");

        const float* sa = smA[c % ST];
        const float* sb = smB[c % ST];

        #pragma unroll
        for (int ks = 0; ks < 2; ++ks) {
            const int k0 = ks * 8;
            uint32_t af[MT][4], bf[4][2];
            #pragma unroll
            for (int mt = 0; mt < MT; ++mt) {
                const float* p = sa + (warp_m * 32 + mt * 16 + g) * PAD + k0;
                af[mt][0] = __float_as_uint(p[tg]);
                af[mt][1] = __float_as_uint(p[8 * PAD + tg]);
                af[mt][2] = __float_as_uint(p[tg + 4]);
                af[mt][3] = __float_as_uint(p[8 * PAD + tg + 4]);
            }
            #pragma unroll
            for (int nt = 0; nt < 4; ++nt) {
                const float* p = sb + (warp_n * 32 + nt * 8 + g) * PAD + k0;
                bf[nt][0] = __float_as_uint(p[tg]);
                bf[nt][1] = __float_as_uint(p[tg + 4]);
            }
            #pragma unroll
            for (int mt = 0; mt < MT; ++mt)
                #pragma unroll
                for (int nt = 0; nt < 4; ++nt)
                    mma_tf32(acc[mt][nt], af[mt], bf[nt]);
        }
    }

    float* Cm = (SPLITK > 1) ? (Cout + (size_t)z * M * N) : Cout;
    const int row_base = blockIdx.y * BM + warp_m * 32;
    const int col_base = blockIdx.x * BN + warp_n * 32;
    #pragma unroll
    for (int mt = 0; mt < MT; ++mt) {
        #pragma unroll
        for (int nt = 0; nt < 4; ++nt) {
            int r0 = row_base + mt * 16 + g;
            int c0 = col_base + nt * 8 + 2 * tg;
            float b0 = 0.f, b1 = 0.f;
            if (SPLITK == 1) { b0 = bias[c0]; b1 = bias[c0 + 1]; }
            #pragma unroll
            for (int half = 0; half < 2; ++half) {
                int r = r0 + half * 8;
                float v0 = acc[mt][nt][half * 2 + 0] + b0;
                float v1 = acc[mt][nt][half * 2 + 1] + b1;
                size_t off = (size_t)r * N + c0;
                if (RES) {
                    float2 rv = *(const float2*)(res + off);
                    v0 += rv.x; v1 += rv.y;
                }
                if (GELU) {
                    v0 = 0.5f * v0 * (1.0f + erff(v0 * 0.70710678118654752f));
                    v1 = 0.5f * v1 * (1.0f + erff(v1 * 0.70710678118654752f));
                }
                float2 ov; ov.x = v0; ov.y = v1;
                *(float2*)(Cm + off) = ov;
            }
        }
    }
}

// ---------------------------------------------------------------------------
// Split-K combine (fc2): out = p0 + p1 + bias + res
// ---------------------------------------------------------------------------
__global__ __launch_bounds__(256) void sk_combine(
    const float* __restrict__ part, const float* __restrict__ bias,
    const float* __restrict__ res, float* __restrict__ out, int total4)
{
    int i = blockIdx.x * 256 + threadIdx.x;
    if (i >= total4) return;
    int col = (i << 2) & (C_DIM - 1);
    float4 p0 = ((const float4*)part)[i];
    float4 p1 = ((const float4*)part)[i + (M_ROWS * C_DIM / 4)];
    float4 bv = *(const float4*)(bias + col);
    float4 rv = ((const float4*)res)[i];
    float4 o;
    o.x = p0.x + p1.x + bv.x + rv.x;
    o.y = p0.y + p1.y + bv.y + rv.y;
    o.z = p0.z + p1.z + bv.z + rv.z;
    o.w = p0.w + p1.w + bv.w + rv.w;
    ((float4*)out)[i] = o;
}

// ---------------------------------------------------------------------------
// proj combine + LN2 fused: x2 = p0+p1+proj_b+x; h = LN(x2, w, b)
// one block (128 threads) per row
// ---------------------------------------------------------------------------
__global__ __launch_bounds__(128) void combine_ln(
    const float* __restrict__ part, const float* __restrict__ bias,
    const float* __restrict__ res, const float* __restrict__ w,
    const float* __restrict__ b, float* __restrict__ x2,
    float* __restrict__ h)
{
    int row = blockIdx.x;
    int tid = threadIdx.x;
    size_t idx = (size_t)row * (C_DIM / 4) + tid;
    float4 p0 = ((const float4*)part)[idx];
    float4 p1 = ((const float4*)part)[idx + (M_ROWS * C_DIM / 4)];
    float4 bv = ((const float4*)bias)[tid];
    float4 rv = ((const float4*)res)[idx];
    float4 v;
    v.x = p0.x + p1.x + bv.x + rv.x;
    v.y = p0.y + p1.y + bv.y + rv.y;
    v.z = p0.z + p1.z + bv.z + rv.z;
    v.w = p0.w + p1.w + bv.w + rv.w;
    ((float4*)x2)[idx] = v;

    float s  = v.x + v.y + v.z + v.w;
    float sq = v.x*v.x + v.y*v.y + v.z*v.z + v.w*v.w;
    #pragma unroll
    for (int o = 16; o > 0; o >>= 1) {
        s  += __shfl_xor_sync(0xffffffffu, s,  o);
        sq += __shfl_xor_sync(0xffffffffu, sq, o);
    }
    __shared__ float ss[4], ssq[4];
    if ((tid & 31) == 0) { ss[tid >> 5] = s; ssq[tid >> 5] = sq; }
    __syncthreads();
    s  = ss[0]  + ss[1]  + ss[2]  + ss[3];
    sq = ssq[0] + ssq[1] + ssq[2] + ssq[3];
    float mu  = s * (1.0f / C_DIM);
    float var = sq * (1.0f / C_DIM) - mu * mu;
    float inv = rsqrtf(var + 1e-5f);
    float4 wv = ((const float4*)w)[tid];
    float4 bb = ((const float4*)b)[tid];
    float4 o;
    o.x = (v.x - mu) * inv * wv.x + bb.x;
    o.y = (v.y - mu) * inv * wv.y + bb.y;
    o.z = (v.z - mu) * inv * wv.z + bb.z;
    o.w = (v.w - mu) * inv * wv.w + bb.w;
    ((float4*)h)[idx] = o;
}

// ---------------------------------------------------------------------------
// Tiled windowed attention: 512 threads = 16 warps, 4 tokens per warp.
// ---------------------------------------------------------------------------
__global__ __launch_bounds__(512) void attn_kernel(
    const float* __restrict__ qkv, const float* __restrict__ rel_bias,
    float* __restrict__ out, int T)
{
    const int t0 = blockIdx.x * ATT_TT;
    const int h  = blockIdx.y;
    const int n  = blockIdx.z;
    const int tid  = threadIdx.x;
    const int wid  = tid >> 5;
    const int lane = tid & 31;

    extern __shared__ __align__(16) float sm[];
    float* sk = sm;
    float* sv = sk + ATT_SPAN * ATT_LD;
    float* sq = sv + ATT_SPAN * ATT_LD;

    for (int i = tid; i < ATT_SPAN * 16; i += 512) {
        int j  = i >> 4;
        int f4 = (i & 15) << 2;
        int pos = t0 - LEFT + j;
        float4 kv, vv;
        if (pos >= 0 && pos < T) {
            const float* base = qkv + ((size_t)n * T + pos) * QKV_DIM + h * HEAD_D;
            kv = *(const float4*)(base + C_DIM + f4);
            vv = *(const float4*)(base + 2 * C_DIM + f4);
        } else {
            kv = make_float4(0.f, 0.f, 0.f, 0.f);
            vv = make_float4(0.f, 0.f, 0.f, 0.f);
        }
        float* kd = sk + j * ATT_LD + f4;
        float* vd = sv + j * ATT_LD + f4;
        kd[0] = kv.x; kd[1] = kv.y; kd[2] = kv.z; kd[3] = kv.w;
        vd[0] = vv.x; vd[1] = vv.y; vd[2] = vv.z; vd[3] = vv.w;
    }
    for (int i = tid; i < ATT_TT * 16; i += 512) {
        int j  = i >> 4;
        int f4 = (i & 15) << 2;
        const float* base = qkv + ((size_t)n * T + t0 + j) * QKV_DIM + h * HEAD_D;
        float4 qv = *(const float4*)(base + f4);
        float* qd = sq + j * ATT_LD + f4;
        qd[0] = qv.x * 0.125f; qd[1] = qv.y * 0.125f;
        qd[2] = qv.z * 0.125f; qd[3] = qv.w * 0.125f;
    }
    __syncthreads();

    const float bias0 = rel_bias[h * WIN + lane];
    const float bias1 = (lane < WIN - 32) ? rel_bias[h * WIN + lane + 32] : 0.0f;

    #pragma unroll 1
    for (int tt = 0; tt < 4; ++tt) {
        const int tok = wid * 4 + tt;
        const int t   = t0 + tok;
        const float* qrow = sq + tok * ATT_LD;

        float p0, p1;
        {
            int pos = t - LEFT + lane;
            if (pos >= 0 && pos < T) {
                const float* kr = sk + (tok + lane) * ATT_LD;
                float dot = 0.f;
                #pragma unroll
                for (int d = 0; d < HEAD_D; d += 4) {
                    dot += qrow[d]   * kr[d]   + qrow[d+1] * kr[d+1]
                         + qrow[d+2] * kr[d+2] + qrow[d+3] * kr[d+3];
                }
                p0 = dot + bias0;
            } else {
                p0 = bias0 - 100.0f;
            }
        }
        if (lane < WIN - 32) {
            int pos = t - LEFT + lane + 32;
            if (pos >= 0 && pos < T) {
                const float* kr = sk + (tok + lane + 32) * ATT_LD;
                float dot = 0.f;
                #pragma unroll
                for (int d = 0; d < HEAD_D; d += 4) {
                    dot += qrow[d]   * kr[d]   + qrow[d+1] * kr[d+1]
                         + qrow[d+2] * kr[d+2] + qrow[d+3] * kr[d+3];
                }
                p1 = dot + bias1;
            } else {
                p1 = bias1 - 100.0f;
            }
        } else {
            p1 = -1e30f;
        }

        float mx = fmaxf(p0, p1);
        #pragma unroll
        for (int o = 16; o > 0; o >>= 1)
            mx = fmaxf(mx, __shfl_xor_sync(0xffffffffu, mx, o));
        float e0 = expf(p0 - mx);
        float e1 = (lane < WIN - 32) ? expf(p1 - mx) : 0.0f;
        float sum = e0 + e1;
        #pragma unroll
        for (int o = 16; o > 0; o >>= 1)
            sum += __shfl_xor_sync(0xffffffffu, sum, o);
        float rinv = 1.0f / sum;
        e0 *= rinv; e1 *= rinv;

        float acc0 = 0.f, acc1 = 0.f;
        #pragma unroll
        for (int w = 0; w < WIN; ++w) {
            float a = __shfl_sync(0xffffffffu, (w < 32) ? e0 : e1, w & 31);
            const float* vr = sv + (tok + w) * ATT_LD;
            acc0 += a * vr[lane];
            acc1 += a * vr[lane + 32];
        }
        float* orow = out + ((size_t)n * T + t) * C_DIM + h * HEAD_D;
        orow[lane]      = acc0;
        orow[lane + 32] = acc1;
    }
}

// ---------------------------------------------------------------------------
// Launch
// ---------------------------------------------------------------------------
extern "C" void kernel_launch(void* const* d_in, const int* in_sizes, int n_in,
                              void* d_out, int out_size)
{
    const float* x       = (const float*)d_in[0];
    const float* norm1_w = (const float*)d_in[1];
    const float* norm1_b = (const float*)d_in[2];
    const float* qkv_w   = (const float*)d_in[3];
    const float* qkv_b   = (const float*)d_in[4];
    const float* relbias = (const float*)d_in[5];
    const float* proj_w  = (const float*)d_in[6];
    const float* proj_b  = (const float*)d_in[7];
    const float* norm2_w = (const float*)d_in[8];
    const float* norm2_b = (const float*)d_in[9];
    const float* fc1_w   = (const float*)d_in[10];
    const float* fc1_b   = (const float*)d_in[11];
    const float* fc2_w   = (const float*)d_in[12];
    const float* fc2_b   = (const float*)d_in[13];
    float* out = (float*)d_out;

    int M = in_sizes[0] / C_DIM;   // 4096
    int Nb = 2;
    int T = M / Nb;                // 2048

    float *p_h, *p_qkv, *p_att, *p_x2, *p_m1, *p_part;
    cudaGetSymbolAddress((void**)&p_h,    g_h);
    cudaGetSymbolAddress((void**)&p_qkv,  g_qkv);
    cudaGetSymbolAddress((void**)&p_att,  g_att);
    cudaGetSymbolAddress((void**)&p_x2,   g_x2);
    cudaGetSymbolAddress((void**)&p_m1,   g_m1);
    cudaGetSymbolAddress((void**)&p_part, g_part);

    const int ATT_SMEM = (2 * ATT_SPAN * ATT_LD + ATT_TT * ATT_LD) * 4;
    cudaFuncSetAttribute(attn_kernel,
        cudaFuncAttributeMaxDynamicSharedMemorySize, ATT_SMEM);

    const int total4 = M_ROWS * C_DIM / 4;
    const int cblocks = (total4 + 255) / 256;

    // 1) h = LN1(x)
    ln_kernel<<<M, 128>>>(x, norm1_w, norm1_b, p_h);

    // 2) qkv = h @ qkv_w^T + qkv_b        [M,1536]
    tc_gemm_pipe<1, false, false><<<dim3(QKV_DIM / 128, M / 64), 256>>>(
        p_h, qkv_w, qkv_b, nullptr, p_qkv, M, QKV_DIM, C_DIM);

    // 3) windowed attention -> g_att      [M,512]
    attn_kernel<<<dim3(T / ATT_TT, 8, Nb), 512, ATT_SMEM>>>(
        p_qkv, relbias, p_att, T);

    // 4) proj split-K partials, then fused combine + LN2
    tc_gemm_pipe<2, false, false><<<dim3(C_DIM / 128, M / 64, 2), 256>>>(
        p_att, proj_w, nullptr, nullptr, p_part, M, C_DIM, C_DIM);
    combine_ln<<<M, 128>>>(p_part, proj_b, x, norm2_w, norm2_b, p_x2, p_h);

    // 5) m1 = gelu(h @ fc1_w^T + fc1_b)   [M,2048]
    tc_gemm_pipe<1, false, true><<<dim3(HID_DIM / 128, M / 64), 256>>>(
        p_h, fc1_w, fc1_b, nullptr, p_m1, M, HID_DIM, C_DIM);

    // 6) fc2 split-K partials, then combine
    tc_gemm_pipe<2, false, false><<<dim3(C_DIM / 128, M / 64, 2), 256>>>(
        p_m1, fc2_w, nullptr, nullptr, p_part, M, C_DIM, HID_DIM);
    sk_combine<<<cblocks, 256>>>(p_part, fc2_b, p_x2, out, total4);
}

// round 8
// speedup vs baseline: 1.0436x; 1.0436x over previous
#include <cuda_runtime.h>
#include <math.h>
#include <stdint.h>

// ---------------------------------------------------------------------------
// Shapes: x (N=2, T=2048, C=512), H=8, hd=64, WIN=63, LEFT=31, hid=2048
// ---------------------------------------------------------------------------
#define C_DIM   512
#define HID_DIM 2048
#define QKV_DIM 1536
#define HEAD_D  64
#define WIN     63
#define LEFT    31
#define M_ROWS  4096

#define PAD 20

// attention tiling
#define ATT_TT   64
#define ATT_SPAN (ATT_TT + WIN - 1) // 126
#define ATT_LD   65

// ---------------------------------------------------------------------------
// Scratch
// ---------------------------------------------------------------------------
__device__ float g_h   [M_ROWS * C_DIM];
__device__ float g_qkv [M_ROWS * QKV_DIM];
__device__ float g_att [M_ROWS * C_DIM];
__device__ float g_x2  [M_ROWS * C_DIM];
__device__ float g_m1  [M_ROWS * HID_DIM];
__device__ float g_part[2 * M_ROWS * C_DIM];

// ---------------------------------------------------------------------------
// PTX helpers
// ---------------------------------------------------------------------------
__device__ __forceinline__ void cp_async16(void* smem, const void* gmem) {
    uint32_t s = (uint32_t)__cvta_generic_to_shared(smem);
    asm volatile("cp.async.cg.shared.global [%0], [%1], 16;\n" :: "r"(s), "l"(gmem));
}
__device__ __forceinline__ void mma_tf32(float* c, const uint32_t* a, const uint32_t* b) {
    asm volatile(
        "mma.sync.aligned.m16n8k8.row.col.f32.tf32.tf32.f32 "
        "{%0,%1,%2,%3}, {%4,%5,%6,%7}, {%8,%9}, {%0,%1,%2,%3};\n"
        : "+f"(c[0]), "+f"(c[1]), "+f"(c[2]), "+f"(c[3])
        : "r"(a[0]), "r"(a[1]), "r"(a[2]), "r"(a[3]), "r"(b[0]), "r"(b[1]));
}

// ---------------------------------------------------------------------------
// LayerNorm (LN1)
// ---------------------------------------------------------------------------
__global__ __launch_bounds__(128) void ln_kernel(
    const float* __restrict__ x, const float* __restrict__ w,
    const float* __restrict__ b, float* __restrict__ out)
{
    int row = blockIdx.x;
    int tid = threadIdx.x;
    const float4* xr = (const float4*)(x + (size_t)row * C_DIM);
    float4 v = xr[tid];
    float s  = v.x + v.y + v.z + v.w;
    float sq = v.x*v.x + v.y*v.y + v.z*v.z + v.w*v.w;
    #pragma unroll
    for (int o = 16; o > 0; o >>= 1) {
        s  += __shfl_xor_sync(0xffffffffu, s,  o);
        sq += __shfl_xor_sync(0xffffffffu, sq, o);
    }
    __shared__ float ss[4], ssq[4];
    if ((tid & 31) == 0) { ss[tid >> 5] = s; ssq[tid >> 5] = sq; }
    __syncthreads();
    s  = ss[0]  + ss[1]  + ss[2]  + ss[3];
    sq = ssq[0] + ssq[1] + ssq[2] + ssq[3];
    float mu  = s * (1.0f / C_DIM);
    float var = sq * (1.0f / C_DIM) - mu * mu;
    float inv = rsqrtf(var + 1e-5f);
    float4 wv = ((const float4*)w)[tid];
    float4 bv = ((const float4*)b)[tid];
    float4 o;
    o.x = (v.x - mu) * inv * wv.x + bv.x;
    o.y = (v.y - mu) * inv * wv.y + bv.y;
    o.z = (v.z - mu) * inv * wv.z + bv.z;
    o.w = (v.w - mu) * inv * wv.w + bv.w;
    ((float4*)(out + (size_t)row * C_DIM))[tid] = o;
}

// ---------------------------------------------------------------------------
// MT4 GEMM (qkv, fc1): BM=128, BN=128, BK=16, warp tile 64x32, 3-stage,
// single sync per chunk, register fragment prefetch, (256,2), dynamic smem.
// ---------------------------------------------------------------------------
template<bool GELU>
__global__ __launch_bounds__(256, 2) void tc_gemm_mt4(
    const float* __restrict__ A, const float* __restrict__ B,
    const float* __restrict__ bias, float* __restrict__ Cm,
    int M, int N, int K)
{
    constexpr int BM = 128, BN = 128, BK = 16, ST = 3, MT = 4;
    constexpr int SSTRIDE = 2 * BM * PAD;         // floats per stage (A+B)

    extern __shared__ __align__(16) float dsm[];

    const int tid    = threadIdx.x;
    const int wid    = tid >> 5;
    const int lane   = tid & 31;
    const int g      = lane >> 2;
    const int tg     = lane & 3;
    const int warp_m = wid & 1;      // 64 rows
    const int warp_n = wid >> 1;     // 32 cols

    const float* Ab = A + (size_t)blockIdx.y * BM * K;
    const float* Bb = B + (size_t)blockIdx.x * BN * K;

    float acc[MT][4][4];
    #pragma unroll
    for (int mt = 0; mt < MT; mt++)
        #pragma unroll
        for (int nt = 0; nt < 4; nt++)
            #pragma unroll
            for (int i = 0; i < 4; i++) acc[mt][nt][i] = 0.0f;

    // per chunk: A = 128x16 = 512 float4 (2/thread); B same
    auto load_chunk = [&](int buf, int k0) {
        float* da = dsm + buf * SSTRIDE;
        float* db = da + BM * PAD;
        #pragma unroll
        for (int it = 0; it < 2; ++it) {
            int i = tid + it * 256;
            int r = i >> 2;
            int q = (i & 3) << 2;
            cp_async16(&da[r * PAD + q], Ab + (size_t)r * K + k0 + q);
            cp_async16(&db[r * PAD + q], Bb + (size_t)r * K + k0 + q);
        }
    };

    const int nch = K / BK;
    load_chunk(0, 0);
    asm volatile("cp.async.commit_group;");
    load_chunk(1, BK);
    asm volatile("cp.async.commit_group;");

    for (int c = 0; c < nch; ++c) {
        asm volatile("cp.async.wait_group 1;");
        __syncthreads();

        if (c + 2 < nch) load_chunk((c + 2) % ST, (c + 2) * BK);
        asm volatile("cp.async.commit_group;");

        const float* sa = dsm + (c % ST) * SSTRIDE;
        const float* sb = sa + BM * PAD;

        // fragment double buffer over the two ks steps
        uint32_t af[2][MT][4], bf[2][4][2];
        #pragma unroll
        for (int mt = 0; mt < MT; ++mt) {
            const float* p = sa + (warp_m * 64 + mt * 16 + g) * PAD;
            af[0][mt][0] = __float_as_uint(p[tg]);
            af[0][mt][1] = __float_as_uint(p[8 * PAD + tg]);
            af[0][mt][2] = __float_as_uint(p[tg + 4]);
            af[0][mt][3] = __float_as_uint(p[8 * PAD + tg + 4]);
        }
        #pragma unroll
        for (int nt = 0; nt < 4; ++nt) {
            const float* p = sb + (warp_n * 32 + nt * 8 + g) * PAD;
            bf[0][nt][0] = __float_as_uint(p[tg]);
            bf[0][nt][1] = __float_as_uint(p[tg + 4]);
        }
        // prefetch ks=1 fragments, then mma ks=0, then mma ks=1
        #pragma unroll
        for (int mt = 0; mt < MT; ++mt) {
            const float* p = sa + (warp_m * 64 + mt * 16 + g) * PAD + 8;
            af[1][mt][0] = __float_as_uint(p[tg]);
            af[1][mt][1] = __float_as_uint(p[8 * PAD + tg]);
            af[1][mt][2] = __float_as_uint(p[tg + 4]);
            af[1][mt][3] = __float_as_uint(p[8 * PAD + tg + 4]);
        }
        #pragma unroll
        for (int nt = 0; nt < 4; ++nt) {
            const float* p = sb + (warp_n * 32 + nt * 8 + g) * PAD + 8;
            bf[1][nt][0] = __float_as_uint(p[tg]);
            bf[1][nt][1] = __float_as_uint(p[tg + 4]);
        }
        #pragma unroll
        for (int ks = 0; ks < 2; ++ks)
            #pragma unroll
            for (int mt = 0; mt < MT; ++mt)
                #pragma unroll
                for (int nt = 0; nt < 4; ++nt)
                    mma_tf32(acc[mt][nt], af[ks][mt], bf[ks][nt]);
    }

    const int row_base = blockIdx.y * BM + warp_m * 64;
    const int col_base = blockIdx.x * BN + warp_n * 32;
    #pragma unroll
    for (int mt = 0; mt < MT; ++mt) {
        #pragma unroll
        for (int nt = 0; nt < 4; ++nt) {
            int r0 = row_base + mt * 16 + g;
            int c0 = col_base + nt * 8 + 2 * tg;
            float b0 = bias[c0], b1 = bias[c0 + 1];
            #pragma unroll
            for (int half = 0; half < 2; ++half) {
                int r = r0 + half * 8;
                float v0 = acc[mt][nt][half * 2 + 0] + b0;
                float v1 = acc[mt][nt][half * 2 + 1] + b1;
                if (GELU) {
                    v0 = 0.5f * v0 * (1.0f + erff(v0 * 0.70710678118654752f));
                    v1 = 0.5f * v1 * (1.0f + erff(v1 * 0.70710678118654752f));
                }
                float2 ov; ov.x = v0; ov.y = v1;
                *(float2*)(Cm + (size_t)r * N + c0) = ov;
            }
        }
    }
}

// ---------------------------------------------------------------------------
// Split-K GEMM (proj, fc2): BM=64, BN=128, BK=16, 3-stage, (256,3). Partials.
// ---------------------------------------------------------------------------
__global__ __launch_bounds__(256, 3) void tc_gemm_sk(
    const float* __restrict__ A, const float* __restrict__ B,
    float* __restrict__ part, int M, int N, int K)
{
    constexpr int BM = 64, BN = 128, BK = 16, ST = 3;
    constexpr int MT = 2;

    __shared__ __align__(16) float smA[ST][BM * PAD];
    __shared__ __align__(16) float smB[ST][BN * PAD];

    const int tid    = threadIdx.x;
    const int wid    = tid >> 5;
    const int lane   = tid & 31;
    const int g      = lane >> 2;
    const int tg     = lane & 3;
    const int warp_m = wid & 1;
    const int warp_n = wid >> 1;

    const int Kh = K >> 1;
    const int z  = blockIdx.z;

    const float* Ab = A + (size_t)blockIdx.y * BM * K + (size_t)z * Kh;
    const float* Bb = B + (size_t)blockIdx.x * BN * K + (size_t)z * Kh;

    float acc[MT][4][4];
    #pragma unroll
    for (int mt = 0; mt < MT; mt++)
        #pragma unroll
        for (int nt = 0; nt < 4; nt++)
            #pragma unroll
            for (int i = 0; i < 4; i++) acc[mt][nt][i] = 0.0f;

    const int arow = tid >> 2;
    const int aq   = (tid & 3) << 2;
    auto load_chunk = [&](int buf, int k0) {
        cp_async16(&smA[buf][arow * PAD + aq], Ab + (size_t)arow * K + k0 + aq);
        #pragma unroll
        for (int it = 0; it < 2; ++it) {
            int i = tid + it * 256;
            int r = i >> 2;
            int q = (i & 3) << 2;
            cp_async16(&smB[buf][r * PAD + q], Bb + (size_t)r * K + k0 + q);
        }
    };

    const int nch = Kh / BK;
    load_chunk(0, 0);
    asm volatile("cp.async.commit_group;");
    load_chunk(1, BK);
    asm volatile("cp.async.commit_group;");

    for (int c = 0; c < nch; ++c) {
        asm volatile("cp.async.wait_group 1;");
        __syncthreads();

        if (c + 2 < nch) load_chunk((c + 2) % ST, (c + 2) * BK);
        asm volatile("cp.async.commit_group;");

        const float* sa = smA[c % ST];
        const float* sb = smB[c % ST];

        #pragma unroll
        for (int ks = 0; ks < 2; ++ks) {
            const int k0 = ks * 8;
            uint32_t af[MT][4], bf[4][2];
            #pragma unroll
            for (int mt = 0; mt < MT; ++mt) {
                const float* p = sa + (warp_m * 32 + mt * 16 + g) * PAD + k0;
                af[mt][0] = __float_as_uint(p[tg]);
                af[mt][1] = __float_as_uint(p[8 * PAD + tg]);
                af[mt][2] = __float_as_uint(p[tg + 4]);
                af[mt][3] = __float_as_uint(p[8 * PAD + tg + 4]);
            }
            #pragma unroll
            for (int nt = 0; nt < 4; ++nt) {
                const float* p = sb + (warp_n * 32 + nt * 8 + g) * PAD + k0;
                bf[nt][0] = __float_as_uint(p[tg]);
                bf[nt][1] = __float_as_uint(p[tg + 4]);
            }
            #pragma unroll
            for (int mt = 0; mt < MT; ++mt)
                #pragma unroll
                for (int nt = 0; nt < 4; ++nt)
                    mma_tf32(acc[mt][nt], af[mt], bf[nt]);
        }
    }

    float* po = part + (size_t)z * M * N;
    const int row_base = blockIdx.y * BM + warp_m * 32;
    const int col_base = blockIdx.x * BN + warp_n * 32;
    #pragma unroll
    for (int mt = 0; mt < MT; ++mt) {
        #pragma unroll
        for (int nt = 0; nt < 4; ++nt) {
            int r0 = row_base + mt * 16 + g;
            int c0 = col_base + nt * 8 + 2 * tg;
            #pragma unroll
            for (int half = 0; half < 2; ++half) {
                int r = r0 + half * 8;
                float2 ov;
                ov.x = acc[mt][nt][half * 2 + 0];
                ov.y = acc[mt][nt][half * 2 + 1];
                *(float2*)(po + (size_t)r * N + c0) = ov;
            }
        }
    }
}

// ---------------------------------------------------------------------------
// fc2 combine: out = p0 + p1 + bias + res
// ---------------------------------------------------------------------------
__global__ __launch_bounds__(256) void sk_combine(
    const float* __restrict__ part, const float* __restrict__ bias,
    const float* __restrict__ res, float* __restrict__ out, int total4)
{
    int i = blockIdx.x * 256 + threadIdx.x;
    if (i >= total4) return;
    int col = (i << 2) & (C_DIM - 1);
    float4 p0 = ((const float4*)part)[i];
    float4 p1 = ((const float4*)part)[i + (M_ROWS * C_DIM / 4)];
    float4 bv = *(const float4*)(bias + col);
    float4 rv = ((const float4*)res)[i];
    float4 o;
    o.x = p0.x + p1.x + bv.x + rv.x;
    o.y = p0.y + p1.y + bv.y + rv.y;
    o.z = p0.z + p1.z + bv.z + rv.z;
    o.w = p0.w + p1.w + bv.w + rv.w;
    ((float4*)out)[i] = o;
}

// ---------------------------------------------------------------------------
// proj combine + LN2 fused
// ---------------------------------------------------------------------------
__global__ __launch_bounds__(128) void combine_ln(
    const float* __restrict__ part, const float* __restrict__ bias,
    const float* __restrict__ res, const float* __restrict__ w,
    const float* __restrict__ b, float* __restrict__ x2,
    float* __restrict__ h)
{
    int row = blockIdx.x;
    int tid = threadIdx.x;
    size_t idx = (size_t)row * (C_DIM / 4) + tid;
    float4 p0 = ((const float4*)part)[idx];
    float4 p1 = ((const float4*)part)[idx + (M_ROWS * C_DIM / 4)];
    float4 bv = ((const float4*)bias)[tid];
    float4 rv = ((const float4*)res)[idx];
    float4 v;
    v.x = p0.x + p1.x + bv.x + rv.x;
    v.y = p0.y + p1.y + bv.y + rv.y;
    v.z = p0.z + p1.z + bv.z + rv.z;
    v.w = p0.w + p1.w + bv.w + rv.w;
    ((float4*)x2)[idx] = v;

    float s  = v.x + v.y + v.z + v.w;
    float sq = v.x*v.x + v.y*v.y + v.z*v.z + v.w*v.w;
    #pragma unroll
    for (int o = 16; o > 0; o >>= 1) {
        s  += __shfl_xor_sync(0xffffffffu, s,  o);
        sq += __shfl_xor_sync(0xffffffffu, sq, o);
    }
    __shared__ float ss[4], ssq[4];
    if ((tid & 31) == 0) { ss[tid >> 5] = s; ssq[tid >> 5] = sq; }
    __syncthreads();
    s  = ss[0]  + ss[1]  + ss[2]  + ss[3];
    sq = ssq[0] + ssq[1] + ssq[2] + ssq[3];
    float mu  = s * (1.0f / C_DIM);
    float var = sq * (1.0f / C_DIM) - mu * mu;
    float inv = rsqrtf(var + 1e-5f);
    float4 wv = ((const float4*)w)[tid];
    float4 bb = ((const float4*)b)[tid];
    float4 o;
    o.x = (v.x - mu) * inv * wv.x + bb.x;
    o.y = (v.y - mu) * inv * wv.y + bb.y;
    o.z = (v.z - mu) * inv * wv.z + bb.z;
    o.w = (v.w - mu) * inv * wv.w + bb.w;
    ((float4*)h)[idx] = o;
}

// ---------------------------------------------------------------------------
// Tiled windowed attention (R4/R6-proven, 256 threads)
// ---------------------------------------------------------------------------
__global__ __launch_bounds__(256) void attn_kernel(
    const float* __restrict__ qkv, const float* __restrict__ rel_bias,
    float* __restrict__ out, int T)
{
    const int t0 = blockIdx.x * ATT_TT;
    const int h  = blockIdx.y;
    const int n  = blockIdx.z;
    const int tid  = threadIdx.x;
    const int wid  = tid >> 5;
    const int lane = tid & 31;

    extern __shared__ __align__(16) float sm[];
    float* sk = sm;
    float* sv = sk + ATT_SPAN * ATT_LD;
    float* sq = sv + ATT_SPAN * ATT_LD;

    for (int i = tid; i < ATT_SPAN * 16; i += 256) {
        int j  = i >> 4;
        int f4 = (i & 15) << 2;
        int pos = t0 - LEFT + j;
        float4 kv, vv;
        if (pos >= 0 && pos < T) {
            const float* base = qkv + ((size_t)n * T + pos) * QKV_DIM + h * HEAD_D;
            kv = *(const float4*)(base + C_DIM + f4);
            vv = *(const float4*)(base + 2 * C_DIM + f4);
        } else {
            kv = make_float4(0.f, 0.f, 0.f, 0.f);
            vv = make_float4(0.f, 0.f, 0.f, 0.f);
        }
        float* kd = sk + j * ATT_LD + f4;
        float* vd = sv + j * ATT_LD + f4;
        kd[0] = kv.x; kd[1] = kv.y; kd[2] = kv.z; kd[3] = kv.w;
        vd[0] = vv.x; vd[1] = vv.y; vd[2] = vv.z; vd[3] = vv.w;
    }
    for (int i = tid; i < ATT_TT * 16; i += 256) {
        int j  = i >> 4;
        int f4 = (i & 15) << 2;
        const float* base = qkv + ((size_t)n * T + t0 + j) * QKV_DIM + h * HEAD_D;
        float4 qv = *(const float4*)(base + f4);
        float* qd = sq + j * ATT_LD + f4;
        qd[0] = qv.x * 0.125f; qd[1] = qv.y * 0.125f;
        qd[2] = qv.z * 0.125f; qd[3] = qv.w * 0.125f;
    }
    __syncthreads();

    const float bias0 = rel_bias[h * WIN + lane];
    const float bias1 = (lane < WIN - 32) ? rel_bias[h * WIN + lane + 32] : 0.0f;

    #pragma unroll 1
    for (int tt = 0; tt < 8; ++tt) {
        const int tok = wid * 8 + tt;
        const int t   = t0 + tok;
        const float* qrow = sq + tok * ATT_LD;

        float p0, p1;
        {
            int pos = t - LEFT + lane;
            if (pos >= 0 && pos < T) {
                const float* kr = sk + (tok + lane) * ATT_LD;
                float dot = 0.f;
                #pragma unroll
                for (int d = 0; d < HEAD_D; d += 4) {
                    dot += qrow[d]   * kr[d]   + qrow[d+1] * kr[d+1]
                         + qrow[d+2] * kr[d+2] + qrow[d+3] * kr[d+3];
                }
                p0 = dot + bias0;
            } else {
                p0 = bias0 - 100.0f;
            }
        }
        if (lane < WIN - 32) {
            int pos = t - LEFT + lane + 32;
            if (pos >= 0 && pos < T) {
                const float* kr = sk + (tok + lane + 32) * ATT_LD;
                float dot = 0.f;
                #pragma unroll
                for (int d = 0; d < HEAD_D; d += 4) {
                    dot += qrow[d]   * kr[d]   + qrow[d+1] * kr[d+1]
                         + qrow[d+2] * kr[d+2] + qrow[d+3] * kr[d+3];
                }
                p1 = dot + bias1;
            } else {
                p1 = bias1 - 100.0f;
            }
        } else {
            p1 = -1e30f;
        }

        float mx = fmaxf(p0, p1);
        #pragma unroll
        for (int o = 16; o > 0; o >>= 1)
            mx = fmaxf(mx, __shfl_xor_sync(0xffffffffu, mx, o));
        float e0 = expf(p0 - mx);
        float e1 = (lane < WIN - 32) ? expf(p1 - mx) : 0.0f;
        float sum = e0 + e1;
        #pragma unroll
        for (int o = 16; o > 0; o >>= 1)
            sum += __shfl_xor_sync(0xffffffffu, sum, o);
        float rinv = 1.0f / sum;
        e0 *= rinv; e1 *= rinv;

        float acc0 = 0.f, acc1 = 0.f;
        #pragma unroll
        for (int w = 0; w < WIN; ++w) {
            float a = __shfl_sync(0xffffffffu, (w < 32) ? e0 : e1, w & 31);
            const float* vr = sv + (tok + w) * ATT_LD;
            acc0 += a * vr[lane];
            acc1 += a * vr[lane + 32];
        }
        float* orow = out + ((size_t)n * T + t) * C_DIM + h * HEAD_D;
        orow[lane]      = acc0;
        orow[lane + 32] = acc1;
    }
}

// ---------------------------------------------------------------------------
// Launch
// ---------------------------------------------------------------------------
extern "C" void kernel_launch(void* const* d_in, const int* in_sizes, int n_in,
                              void* d_out, int out_size)
{
    const float* x       = (const float*)d_in[0];
    const float* norm1_w = (const float*)d_in[1];
    const float* norm1_b = (const float*)d_in[2];
    const float* qkv_w   = (const float*)d_in[3];
    const float* qkv_b   = (const float*)d_in[4];
    const float* relbias = (const float*)d_in[5];
    const float* proj_w  = (const float*)d_in[6];
    const float* proj_b  = (const float*)d_in[7];
    const float* norm2_w = (const float*)d_in[8];
    const float* norm2_b = (const float*)d_in[9];
    const float* fc1_w   = (const float*)d_in[10];
    const float* fc1_b   = (const float*)d_in[11];
    const float* fc2_w   = (const float*)d_in[12];
    const float* fc2_b   = (const float*)d_in[13];
    float* out = (float*)d_out;

    int M = in_sizes[0] / C_DIM;   // 4096
    int Nb = 2;
    int T = M / Nb;                // 2048

    float *p_h, *p_qkv, *p_att, *p_x2, *p_m1, *p_part;
    cudaGetSymbolAddress((void**)&p_h,    g_h);
    cudaGetSymbolAddress((void**)&p_qkv,  g_qkv);
    cudaGetSymbolAddress((void**)&p_att,  g_att);
    cudaGetSymbolAddress((void**)&p_x2,   g_x2);
    cudaGetSymbolAddress((void**)&p_m1,   g_m1);
    cudaGetSymbolAddress((void**)&p_part, g_part);

    const int ATT_SMEM = (2 * ATT_SPAN * ATT_LD + ATT_TT * ATT_LD) * 4;
    const int MT4_SMEM = 3 * 2 * 128 * PAD * 4;   // 61440
    cudaFuncSetAttribute(attn_kernel,
        cudaFuncAttributeMaxDynamicSharedMemorySize, ATT_SMEM);
    cudaFuncSetAttribute(tc_gemm_mt4<false>,
        cudaFuncAttributeMaxDynamicSharedMemorySize, MT4_SMEM);
    cudaFuncSetAttribute(tc_gemm_mt4<true>,
        cudaFuncAttributeMaxDynamicSharedMemorySize, MT4_SMEM);

    const int total4 = M_ROWS * C_DIM / 4;
    const int cblocks = (total4 + 255) / 256;

    // 1) h = LN1(x)
    ln_kernel<<<M, 128>>>(x, norm1_w, norm1_b, p_h);

    // 2) qkv = h @ qkv_w^T + qkv_b        [M,1536]
    tc_gemm_mt4<false><<<dim3(QKV_DIM / 128, M / 128), 256, MT4_SMEM>>>(
        p_h, qkv_w, qkv_b, p_qkv, M, QKV_DIM, C_DIM);

    // 3) windowed attention -> g_att      [M,512]
    attn_kernel<<<dim3(T / ATT_TT, 8, Nb), 256, ATT_SMEM>>>(
        p_qkv, relbias, p_att, T);

    // 4) proj split-K partials, then fused combine + LN2
    tc_gemm_sk<<<dim3(C_DIM / 128, M / 64, 2), 256>>>(
        p_att, proj_w, p_part, M, C_DIM, C_DIM);
    combine_ln<<<M, 128>>>(p_part, proj_b, x, norm2_w, norm2_b, p_x2, p_h);

    // 5) m1 = gelu(h @ fc1_w^T + fc1_b)   [M,2048]
    tc_gemm_mt4<true><<<dim3(HID_DIM / 128, M / 128), 256, MT4_SMEM>>>(
        p_h, fc1_w, fc1_b, p_m1, M, HID_DIM, C_DIM);

    // 6) fc2 split-K partials, then combine
    tc_gemm_sk<<<dim3(C_DIM / 128, M / 64, 2), 256>>>(
        p_m1, fc2_w, p_part, M, C_DIM, HID_DIM);
    sk_combine<<<cblocks, 256>>>(p_part, fc2_b, p_x2, out, total4);
}

// round 9
// speedup vs baseline: 1.5706x; 1.5049x over previous
#include <cuda_runtime.h>
#include <cuda_fp16.h>
#include <math.h>
#include <stdint.h>

// ---------------------------------------------------------------------------
// Shapes: x (N=2, T=2048, C=512), H=8, hd=64, WIN=63, LEFT=31, hid=2048
// ---------------------------------------------------------------------------
#define C_DIM   512
#define HID_DIM 2048
#define QKV_DIM 1536
#define HEAD_D  64
#define WIN     63
#define LEFT    31
#define M_ROWS  4096

// attention tiling
#define ATT_TT   64
#define ATT_SPAN (ATT_TT + WIN - 1) // 126
#define ATT_LD   65

// fp16 weight buffer offsets (halves)
#define W_QKV  0
#define W_PROJ 786432
#define W_FC1  1048576
#define W_FC2  2097152
#define W_TOT  3145728

// ---------------------------------------------------------------------------
// Scratch
// ---------------------------------------------------------------------------
__device__ __half g_h16  [M_ROWS * C_DIM];
__device__ __half g_qkv16[M_ROWS * QKV_DIM];
__device__ __half g_att16[M_ROWS * C_DIM];
__device__ float  g_x2   [M_ROWS * C_DIM];
__device__ __half g_m1h  [M_ROWS * HID_DIM];
__device__ float  g_part [2 * M_ROWS * C_DIM];
__device__ __half g_w16  [W_TOT];

// ---------------------------------------------------------------------------
// PTX helpers
// ---------------------------------------------------------------------------
__device__ __forceinline__ void cp_async16_s(uint32_t s, const void* g) {
    asm volatile("cp.async.cg.shared.global [%0], [%1], 16;\n" :: "r"(s), "l"(g));
}
__device__ __forceinline__ void ldsm4(uint32_t& r0, uint32_t& r1,
                                      uint32_t& r2, uint32_t& r3, uint32_t addr) {
    asm volatile("ldmatrix.sync.aligned.m8n8.x4.shared.b16 {%0,%1,%2,%3}, [%4];"
        : "=r"(r0), "=r"(r1), "=r"(r2), "=r"(r3) : "r"(addr));
}
__device__ __forceinline__ void mma_f16(float* c, const uint32_t* a, const uint32_t* b) {
    asm volatile(
        "mma.sync.aligned.m16n8k16.row.col.f32.f16.f16.f32 "
        "{%0,%1,%2,%3}, {%4,%5,%6,%7}, {%8,%9}, {%0,%1,%2,%3};\n"
        : "+f"(c[0]), "+f"(c[1]), "+f"(c[2]), "+f"(c[3])
        : "r"(a[0]), "r"(a[1]), "r"(a[2]), "r"(a[3]), "r"(b[0]), "r"(b[1]));
}
__device__ __forceinline__ float4 ld4h(const __half* p) {
    uint2 raw = *(const uint2*)p;
    __half2 h0 = *reinterpret_cast<__half2*>(&raw.x);
    __half2 h1 = *reinterpret_cast<__half2*>(&raw.y);
    float2 f0 = __half22float2(h0), f1 = __half22float2(h1);
    return make_float4(f0.x, f0.y, f1.x, f1.y);
}

// ---------------------------------------------------------------------------
// Weight conversion fp32 -> fp16 (one launch, all four weight matrices)
// ---------------------------------------------------------------------------
__global__ __launch_bounds__(256) void wconv(
    const float* __restrict__ w0, const float* __restrict__ w1,
    const float* __restrict__ w2, const float* __restrict__ w3,
    __half* __restrict__ out)
{
    int i = blockIdx.x * 256 + threadIdx.x;    // float4 index, < 786432
    const float* src; int off;
    if (i < 196608)      { src = w0; off = i; }
    else if (i < 262144) { src = w1; off = i - 196608; }
    else if (i < 524288) { src = w2; off = i - 262144; }
    else                 { src = w3; off = i - 524288; }
    float4 v = ((const float4*)src)[off];
    ((__half2*)out)[2 * i]     = __floats2half2_rn(v.x, v.y);
    ((__half2*)out)[2 * i + 1] = __floats2half2_rn(v.z, v.w);
}

// ---------------------------------------------------------------------------
// LayerNorm (LN1): fp32 in -> fp16 out
// ---------------------------------------------------------------------------
__global__ __launch_bounds__(128) void ln_kernel_h(
    const float* __restrict__ x, const float* __restrict__ w,
    const float* __restrict__ b, __half* __restrict__ out)
{
    int row = blockIdx.x;
    int tid = threadIdx.x;
    const float4* xr = (const float4*)(x + (size_t)row * C_DIM);
    float4 v = xr[tid];
    float s  = v.x + v.y + v.z + v.w;
    float sq = v.x*v.x + v.y*v.y + v.z*v.z + v.w*v.w;
    #pragma unroll
    for (int o = 16; o > 0; o >>= 1) {
        s  += __shfl_xor_sync(0xffffffffu, s,  o);
        sq += __shfl_xor_sync(0xffffffffu, sq, o);
    }
    __shared__ float ss[4], ssq[4];
    if ((tid & 31) == 0) { ss[tid >> 5] = s; ssq[tid >> 5] = sq; }
    __syncthreads();
    s  = ss[0]  + ss[1]  + ss[2]  + ss[3];
    sq = ssq[0] + ssq[1] + ssq[2] + ssq[3];
    float mu  = s * (1.0f / C_DIM);
    float var = sq * (1.0f / C_DIM) - mu * mu;
    float inv = rsqrtf(var + 1e-5f);
    float4 wv = ((const float4*)w)[tid];
    float4 bv = ((const float4*)b)[tid];
    float o0 = (v.x - mu) * inv * wv.x + bv.x;
    float o1 = (v.y - mu) * inv * wv.y + bv.y;
    float o2 = (v.z - mu) * inv * wv.z + bv.z;
    float o3 = (v.w - mu) * inv * wv.w + bv.w;
    __half2* po = (__half2*)(out + (size_t)row * C_DIM);
    po[tid * 2]     = __floats2half2_rn(o0, o1);
    po[tid * 2 + 1] = __floats2half2_rn(o2, o3);
}

// ---------------------------------------------------------------------------
// HGEMM: C[M,N] = A[M,K] @ B[N,K]^T (fp16 in, fp32 acc)
// BM=128, BN=128, BK=32, 3-stage cp.async, ldmatrix fragments, (256,2).
// SPLITK==1: +bias (+GELU), fp16 out.  SPLITK==2: fp32 partials.
// ---------------------------------------------------------------------------
template<int SPLITK, bool GELU>
__global__ __launch_bounds__(256, 2) void hgemm(
    const __half* __restrict__ A, const __half* __restrict__ B,
    const float* __restrict__ bias, void* __restrict__ Cout,
    int M, int N, int K)
{
    constexpr int BM = 128, BN = 128, BK = 32, ST = 3;
    constexpr int SK = 40;                       // halves per smem row
    constexpr int A_BYTES = BM * SK * 2;         // 10240
    constexpr int STAGE_BYTES = 2 * A_BYTES;     // 20480

    extern __shared__ __align__(16) __half hsm[];
    const uint32_t sbase = (uint32_t)__cvta_generic_to_shared(hsm);

    const int tid  = threadIdx.x;
    const int wid  = tid >> 5;
    const int lane = tid & 31;
    const int g    = lane >> 2;
    const int tg   = lane & 3;
    const int warp_m = wid & 1;                  // 64 rows
    const int warp_n = wid >> 1;                 // 32 cols

    const int Kl = K / SPLITK;
    const int z  = (SPLITK > 1) ? blockIdx.z : 0;
    const __half* Ab = A + (size_t)blockIdx.y * BM * K + (size_t)z * Kl;
    const __half* Bb = B + (size_t)blockIdx.x * BN * K + (size_t)z * Kl;

    float acc[4][4][4];
    #pragma unroll
    for (int mt = 0; mt < 4; mt++)
        #pragma unroll
        for (int nt = 0; nt < 4; nt++)
            #pragma unroll
            for (int i = 0; i < 4; i++) acc[mt][nt][i] = 0.0f;

    // ldmatrix per-lane byte offsets within a stage
    const int qh = lane >> 3, rh = lane & 7;
    const uint32_t a_lane =
        (uint32_t)(((warp_m * 64 + rh + 8 * (qh & 1)) * SK + (qh >> 1) * 8) * 2);
    const uint32_t b_lane =
        (uint32_t)(((warp_n * 32 + rh + 8 * (qh & 1)) * SK + (qh >> 1) * 8) * 2)
        + A_BYTES;

    // per chunk: A/B each 128 rows x 64B = 512 x 16B ops; 2 per thread each
    auto load_chunk = [&](int buf, int k0) {
        uint32_t base = sbase + buf * STAGE_BYTES;
        #pragma unroll
        for (int it = 0; it < 2; ++it) {
            int i = tid + it * 256;
            int r = i >> 2, seg = i & 3;
            uint32_t so = (uint32_t)(r * SK + seg * 8) * 2;
            cp_async16_s(base + so,           Ab + (size_t)r * K + k0 + seg * 8);
            cp_async16_s(base + A_BYTES + so, Bb + (size_t)r * K + k0 + seg * 8);
        }
    };

    const int nch = Kl / BK;
    load_chunk(0, 0);
    asm volatile("cp.async.commit_group;");
    load_chunk(1, BK);
    asm volatile("cp.async.commit_group;");

    for (int c = 0; c < nch; ++c) {
        asm volatile("cp.async.wait_group 1;");
        __syncthreads();

        if (c + 2 < nch) load_chunk((c + 2) % ST, (c + 2) * BK);
        asm volatile("cp.async.commit_group;");

        const uint32_t st = sbase + (c % ST) * STAGE_BYTES;
        #pragma unroll
        for (int ks = 0; ks < 2; ++ks) {
            uint32_t aw[4][4], bw[4][2];
            #pragma unroll
            for (int nb = 0; nb < 2; ++nb) {
                uint32_t x0, x1, x2, x3;
                ldsm4(x0, x1, x2, x3, st + b_lane + nb * 1280 + ks * 32);
                bw[nb * 2][0] = x0; bw[nb * 2 + 1][0] = x1;
                bw[nb * 2][1] = x2; bw[nb * 2 + 1][1] = x3;
            }
            #pragma unroll
            for (int mt = 0; mt < 4; ++mt)
                ldsm4(aw[mt][0], aw[mt][1], aw[mt][2], aw[mt][3],
                      st + a_lane + mt * 1280 + ks * 32);
            #pragma unroll
            for (int mt = 0; mt < 4; ++mt)
                #pragma unroll
                for (int nt = 0; nt < 4; ++nt)
                    mma_f16(acc[mt][nt], aw[mt], bw[nt]);
        }
    }

    const int row_base = blockIdx.y * BM + warp_m * 64;
    const int col_base = blockIdx.x * BN + warp_n * 32;

    if (SPLITK == 1) {
        __half* Ch = (__half*)Cout;
        #pragma unroll
        for (int mt = 0; mt < 4; ++mt) {
            #pragma unroll
            for (int nt = 0; nt < 4; ++nt) {
                int r0 = row_base + mt * 16 + g;
                int c0 = col_base + nt * 8 + 2 * tg;
                float b0 = bias[c0], b1 = bias[c0 + 1];
                #pragma unroll
                for (int hh = 0; hh < 2; ++hh) {
                    int r = r0 + hh * 8;
                    float v0 = acc[mt][nt][hh * 2 + 0] + b0;
                    float v1 = acc[mt][nt][hh * 2 + 1] + b1;
                    if (GELU) {
                        v0 = 0.5f * v0 * (1.0f + erff(v0 * 0.70710678118654752f));
                        v1 = 0.5f * v1 * (1.0f + erff(v1 * 0.70710678118654752f));
                    }
                    *(__half2*)(Ch + (size_t)r * N + c0) = __floats2half2_rn(v0, v1);
                }
            }
        }
    } else {
        float* Cp = (float*)Cout + (size_t)z * M * N;
        #pragma unroll
        for (int mt = 0; mt < 4; ++mt) {
            #pragma unroll
            for (int nt = 0; nt < 4; ++nt) {
                int r0 = row_base + mt * 16 + g;
                int c0 = col_base + nt * 8 + 2 * tg;
                #pragma unroll
                for (int hh = 0; hh < 2; ++hh) {
                    int r = r0 + hh * 8;
                    float2 ov;
                    ov.x = acc[mt][nt][hh * 2 + 0];
                    ov.y = acc[mt][nt][hh * 2 + 1];
                    *(float2*)(Cp + (size_t)r * N + c0) = ov;
                }
            }
        }
    }
}

// ---------------------------------------------------------------------------
// fc2 combine: out = p0 + p1 + bias + res   (fp32)
// ---------------------------------------------------------------------------
__global__ __launch_bounds__(256) void sk_combine(
    const float* __restrict__ part, const float* __restrict__ bias,
    const float* __restrict__ res, float* __restrict__ out, int total4)
{
    int i = blockIdx.x * 256 + threadIdx.x;
    if (i >= total4) return;
    int col = (i << 2) & (C_DIM - 1);
    float4 p0 = ((const float4*)part)[i];
    float4 p1 = ((const float4*)part)[i + (M_ROWS * C_DIM / 4)];
    float4 bv = *(const float4*)(bias + col);
    float4 rv = ((const float4*)res)[i];
    float4 o;
    o.x = p0.x + p1.x + bv.x + rv.x;
    o.y = p0.y + p1.y + bv.y + rv.y;
    o.z = p0.z + p1.z + bv.z + rv.z;
    o.w = p0.w + p1.w + bv.w + rv.w;
    ((float4*)out)[i] = o;
}

// ---------------------------------------------------------------------------
// proj combine + LN2 fused: x2 = p0+p1+proj_b+x (fp32); h = LN(x2) (fp16)
// ---------------------------------------------------------------------------
__global__ __launch_bounds__(128) void combine_ln(
    const float* __restrict__ part, const float* __restrict__ bias,
    const float* __restrict__ res, const float* __restrict__ w,
    const float* __restrict__ b, float* __restrict__ x2,
    __half* __restrict__ h)
{
    int row = blockIdx.x;
    int tid = threadIdx.x;
    size_t idx = (size_t)row * (C_DIM / 4) + tid;
    float4 p0 = ((const float4*)part)[idx];
    float4 p1 = ((const float4*)part)[idx + (M_ROWS * C_DIM / 4)];
    float4 bv = ((const float4*)bias)[tid];
    float4 rv = ((const float4*)res)[idx];
    float4 v;
    v.x = p0.x + p1.x + bv.x + rv.x;
    v.y = p0.y + p1.y + bv.y + rv.y;
    v.z = p0.z + p1.z + bv.z + rv.z;
    v.w = p0.w + p1.w + bv.w + rv.w;
    ((float4*)x2)[idx] = v;

    float s  = v.x + v.y + v.z + v.w;
    float sq = v.x*v.x + v.y*v.y + v.z*v.z + v.w*v.w;
    #pragma unroll
    for (int o = 16; o > 0; o >>= 1) {
        s  += __shfl_xor_sync(0xffffffffu, s,  o);
        sq += __shfl_xor_sync(0xffffffffu, sq, o);
    }
    __shared__ float ss[4], ssq[4];
    if ((tid & 31) == 0) { ss[tid >> 5] = s; ssq[tid >> 5] = sq; }
    __syncthreads();
    s  = ss[0]  + ss[1]  + ss[2]  + ss[3];
    sq = ssq[0] + ssq[1] + ssq[2] + ssq[3];
    float mu  = s * (1.0f / C_DIM);
    float var = sq * (1.0f / C_DIM) - mu * mu;
    float inv = rsqrtf(var + 1e-5f);
    float4 wv = ((const float4*)w)[tid];
    float4 bb = ((const float4*)b)[tid];
    float o0 = (v.x - mu) * inv * wv.x + bb.x;
    float o1 = (v.y - mu) * inv * wv.y + bb.y;
    float o2 = (v.z - mu) * inv * wv.z + bb.z;
    float o3 = (v.w - mu) * inv * wv.w + bb.w;
    __half2* ph = (__half2*)h;
    ph[idx * 2]     = __floats2half2_rn(o0, o1);
    ph[idx * 2 + 1] = __floats2half2_rn(o2, o3);
}

// ---------------------------------------------------------------------------
// Tiled windowed attention: fp16 qkv in, fp16 att out; fp32 internals.
// block = 64 tokens x 1 head, 256 threads = 8 warps x 8 tokens.
// ---------------------------------------------------------------------------
__global__ __launch_bounds__(256) void attn_kernel(
    const __half* __restrict__ qkv, const float* __restrict__ rel_bias,
    __half* __restrict__ out, int T)
{
    const int t0 = blockIdx.x * ATT_TT;
    const int h  = blockIdx.y;
    const int n  = blockIdx.z;
    const int tid  = threadIdx.x;
    const int wid  = tid >> 5;
    const int lane = tid & 31;

    extern __shared__ __align__(16) float sm[];
    float* sk = sm;
    float* sv = sk + ATT_SPAN * ATT_LD;
    float* sq = sv + ATT_SPAN * ATT_LD;

    for (int i = tid; i < ATT_SPAN * 16; i += 256) {
        int j  = i >> 4;
        int f4 = (i & 15) << 2;
        int pos = t0 - LEFT + j;
        float4 kv, vv;
        if (pos >= 0 && pos < T) {
            const __half* base = qkv + ((size_t)n * T + pos) * QKV_DIM + h * HEAD_D;
            kv = ld4h(base + C_DIM + f4);
            vv = ld4h(base + 2 * C_DIM + f4);
        } else {
            kv = make_float4(0.f, 0.f, 0.f, 0.f);
            vv = make_float4(0.f, 0.f, 0.f, 0.f);
        }
        float* kd = sk + j * ATT_LD + f4;
        float* vd = sv + j * ATT_LD + f4;
        kd[0] = kv.x; kd[1] = kv.y; kd[2] = kv.z; kd[3] = kv.w;
        vd[0] = vv.x; vd[1] = vv.y; vd[2] = vv.z; vd[3] = vv.w;
    }
    for (int i = tid; i < ATT_TT * 16; i += 256) {
        int j  = i >> 4;
        int f4 = (i & 15) << 2;
        const __half* base = qkv + ((size_t)n * T + t0 + j) * QKV_DIM + h * HEAD_D;
        float4 qv = ld4h(base + f4);
        float* qd = sq + j * ATT_LD + f4;
        qd[0] = qv.x * 0.125f; qd[1] = qv.y * 0.125f;
        qd[2] = qv.z * 0.125f; qd[3] = qv.w * 0.125f;
    }
    __syncthreads();

    const float bias0 = rel_bias[h * WIN + lane];
    const float bias1 = (lane < WIN - 32) ? rel_bias[h * WIN + lane + 32] : 0.0f;

    #pragma unroll 1
    for (int tt = 0; tt < 8; ++tt) {
        const int tok = wid * 8 + tt;
        const int t   = t0 + tok;
        const float* qrow = sq + tok * ATT_LD;

        float p0, p1;
        {
            int pos = t - LEFT + lane;
            if (pos >= 0 && pos < T) {
                const float* kr = sk + (tok + lane) * ATT_LD;
                float dot = 0.f;
                #pragma unroll
                for (int d = 0; d < HEAD_D; d += 4) {
                    dot += qrow[d]   * kr[d]   + qrow[d+1] * kr[d+1]
                         + qrow[d+2] * kr[d+2] + qrow[d+3] * kr[d+3];
                }
                p0 = dot + bias0;
            } else {
                p0 = bias0 - 100.0f;
            }
        }
        if (lane < WIN - 32) {
            int pos = t - LEFT + lane + 32;
            if (pos >= 0 && pos < T) {
                const float* kr = sk + (tok + lane + 32) * ATT_LD;
                float dot = 0.f;
                #pragma unroll
                for (int d = 0; d < HEAD_D; d += 4) {
                    dot += qrow[d]   * kr[d]   + qrow[d+1] * kr[d+1]
                         + qrow[d+2] * kr[d+2] + qrow[d+3] * kr[d+3];
                }
                p1 = dot + bias1;
            } else {
                p1 = bias1 - 100.0f;
            }
        } else {
            p1 = -1e30f;
        }

        float mx = fmaxf(p0, p1);
        #pragma unroll
        for (int o = 16; o > 0; o >>= 1)
            mx = fmaxf(mx, __shfl_xor_sync(0xffffffffu, mx, o));
        float e0 = expf(p0 - mx);
        float e1 = (lane < WIN - 32) ? expf(p1 - mx) : 0.0f;
        float sum = e0 + e1;
        #pragma unroll
        for (int o = 16; o > 0; o >>= 1)
            sum += __shfl_xor_sync(0xffffffffu, sum, o);
        float rinv = 1.0f / sum;
        e0 *= rinv; e1 *= rinv;

        float acc0 = 0.f, acc1 = 0.f;
        #pragma unroll
        for (int w = 0; w < WIN; ++w) {
            float a = __shfl_sync(0xffffffffu, (w < 32) ? e0 : e1, w & 31);
            const float* vr = sv + (tok + w) * ATT_LD;
            acc0 += a * vr[lane];
            acc1 += a * vr[lane + 32];
        }
        __half* orow = out + ((size_t)n * T + t) * C_DIM + h * HEAD_D;
        orow[lane]      = __float2half(acc0);
        orow[lane + 32] = __float2half(acc1);
    }
}

// ---------------------------------------------------------------------------
// Launch
// ---------------------------------------------------------------------------
extern "C" void kernel_launch(void* const* d_in, const int* in_sizes, int n_in,
                              void* d_out, int out_size)
{
    const float* x       = (const float*)d_in[0];
    const float* norm1_w = (const float*)d_in[1];
    const float* norm1_b = (const float*)d_in[2];
    const float* qkv_w   = (const float*)d_in[3];
    const float* qkv_b   = (const float*)d_in[4];
    const float* relbias = (const float*)d_in[5];
    const float* proj_w  = (const float*)d_in[6];
    const float* proj_b  = (const float*)d_in[7];
    const float* norm2_w = (const float*)d_in[8];
    const float* norm2_b = (const float*)d_in[9];
    const float* fc1_w   = (const float*)d_in[10];
    const float* fc1_b   = (const float*)d_in[11];
    const float* fc2_w   = (const float*)d_in[12];
    const float* fc2_b   = (const float*)d_in[13];
    float* out = (float*)d_out;

    int M = in_sizes[0] / C_DIM;   // 4096
    int Nb = 2;
    int T = M / Nb;                // 2048

    __half *p_h16, *p_qkv16, *p_att16, *p_m1h, *p_w16;
    float *p_x2, *p_part;
    cudaGetSymbolAddress((void**)&p_h16,   g_h16);
    cudaGetSymbolAddress((void**)&p_qkv16, g_qkv16);
    cudaGetSymbolAddress((void**)&p_att16, g_att16);
    cudaGetSymbolAddress((void**)&p_x2,    g_x2);
    cudaGetSymbolAddress((void**)&p_m1h,   g_m1h);
    cudaGetSymbolAddress((void**)&p_part,  g_part);
    cudaGetSymbolAddress((void**)&p_w16,   g_w16);

    const int ATT_SMEM = (2 * ATT_SPAN * ATT_LD + ATT_TT * ATT_LD) * 4;
    const int HG_SMEM  = 3 * 20480;   // 61440
    cudaFuncSetAttribute(attn_kernel,
        cudaFuncAttributeMaxDynamicSharedMemorySize, ATT_SMEM);
    cudaFuncSetAttribute(hgemm<1, false>,
        cudaFuncAttributeMaxDynamicSharedMemorySize, HG_SMEM);
    cudaFuncSetAttribute(hgemm<1, true>,
        cudaFuncAttributeMaxDynamicSharedMemorySize, HG_SMEM);
    cudaFuncSetAttribute(hgemm<2, false>,
        cudaFuncAttributeMaxDynamicSharedMemorySize, HG_SMEM);

    const int total4 = M_ROWS * C_DIM / 4;
    const int cblocks = (total4 + 255) / 256;

    // 0) convert weights to fp16 (persistent buffer)
    wconv<<<3072, 256>>>(qkv_w, proj_w, fc1_w, fc2_w, p_w16);

    // 1) h = LN1(x) -> fp16
    ln_kernel_h<<<M, 128>>>(x, norm1_w, norm1_b, p_h16);

    // 2) qkv = h @ qkv_w^T + qkv_b -> fp16   [M,1536]
    hgemm<1, false><<<dim3(QKV_DIM / 128, M / 128), 256, HG_SMEM>>>(
        p_h16, p_w16 + W_QKV, qkv_b, p_qkv16, M, QKV_DIM, C_DIM);

    // 3) windowed attention -> fp16          [M,512]
    attn_kernel<<<dim3(T / ATT_TT, 8, Nb), 256, ATT_SMEM>>>(
        p_qkv16, relbias, p_att16, T);

    // 4) proj split-K partials, then fused combine + LN2
    hgemm<2, false><<<dim3(C_DIM / 128, M / 128, 2), 256, HG_SMEM>>>(
        p_att16, p_w16 + W_PROJ, nullptr, p_part, M, C_DIM, C_DIM);
    combine_ln<<<M, 128>>>(p_part, proj_b, x, norm2_w, norm2_b, p_x2, p_h16);

    // 5) m1 = gelu(h @ fc1_w^T + fc1_b) -> fp16  [M,2048]
    hgemm<1, true><<<dim3(HID_DIM / 128, M / 128), 256, HG_SMEM>>>(
        p_h16, p_w16 + W_FC1, fc1_b, p_m1h, M, HID_DIM, C_DIM);

    // 6) fc2 split-K partials, then combine
    hgemm<2, false><<<dim3(C_DIM / 128, M / 128, 2), 256, HG_SMEM>>>(
        p_m1h, p_w16 + W_FC2, nullptr, p_part, M, C_DIM, HID_DIM);
    sk_combine<<<cblocks, 256>>>(p_part, fc2_b, p_x2, out, total4);
}

// round 10
// speedup vs baseline: 2.1629x; 1.3771x over previous
#include <cuda_runtime.h>
#include <cuda_fp16.h>
#include <math.h>
#include <stdint.h>

// ---------------------------------------------------------------------------
// Shapes: x (N=2, T=2048, C=512), H=8, hd=64, WIN=63, LEFT=31, hid=2048
// ---------------------------------------------------------------------------
#define C_DIM   512
#define HID_DIM 2048
#define QKV_DIM 1536
#define HEAD_D  64
#define WIN     63
#define LEFT    31
#define M_ROWS  4096

// fp16 weight buffer offsets (halves)
#define W_QKV  0
#define W_PROJ 786432
#define W_FC1  1048576
#define W_FC2  2097152
#define W_TOT  3145728

// flash-attention tiling
#define FA_TOK  128                 // tokens per block
#define FA_SPAN 192                 // padded K/V span rows (190 real)
#define FA_REAL (FA_TOK + WIN - 1)  // 190
#define FA_STR  72                  // smem row stride in halves

// ---------------------------------------------------------------------------
// Scratch
// ---------------------------------------------------------------------------
__device__ __half g_h16  [M_ROWS * C_DIM];
__device__ __half g_qkv16[M_ROWS * QKV_DIM];
__device__ __half g_att16[M_ROWS * C_DIM];
__device__ float  g_x2   [M_ROWS * C_DIM];
__device__ __half g_m1h  [M_ROWS * HID_DIM];
__device__ float  g_part [2 * M_ROWS * C_DIM];
__device__ __half g_w16  [W_TOT];

// ---------------------------------------------------------------------------
// PTX helpers
// ---------------------------------------------------------------------------
__device__ __forceinline__ void cp_async16_s(uint32_t s, const void* g) {
    asm volatile("cp.async.cg.shared.global [%0], [%1], 16;\n" :: "r"(s), "l"(g));
}
__device__ __forceinline__ void ldsm4(uint32_t& r0, uint32_t& r1,
                                      uint32_t& r2, uint32_t& r3, uint32_t addr) {
    asm volatile("ldmatrix.sync.aligned.m8n8.x4.shared.b16 {%0,%1,%2,%3}, [%4];"
        : "=r"(r0), "=r"(r1), "=r"(r2), "=r"(r3) : "r"(addr));
}
__device__ __forceinline__ void ldsm4t(uint32_t& r0, uint32_t& r1,
                                       uint32_t& r2, uint32_t& r3, uint32_t addr) {
    asm volatile("ldmatrix.sync.aligned.m8n8.x4.trans.shared.b16 {%0,%1,%2,%3}, [%4];"
        : "=r"(r0), "=r"(r1), "=r"(r2), "=r"(r3) : "r"(addr));
}
__device__ __forceinline__ void mma_f16(float* c, const uint32_t* a, const uint32_t* b) {
    asm volatile(
        "mma.sync.aligned.m16n8k16.row.col.f32.f16.f16.f32 "
        "{%0,%1,%2,%3}, {%4,%5,%6,%7}, {%8,%9}, {%0,%1,%2,%3};\n"
        : "+f"(c[0]), "+f"(c[1]), "+f"(c[2]), "+f"(c[3])
        : "r"(a[0]), "r"(a[1]), "r"(a[2]), "r"(a[3]), "r"(b[0]), "r"(b[1]));
}
__device__ __forceinline__ uint32_t packh2(float a, float b) {
    __half2 h = __floats2half2_rn(a, b);
    return *reinterpret_cast<uint32_t*>(&h);
}

// ---------------------------------------------------------------------------
// Weight conversion fp32 -> fp16
// ---------------------------------------------------------------------------
__global__ __launch_bounds__(256) void wconv(
    const float* __restrict__ w0, const float* __restrict__ w1,
    const float* __restrict__ w2, const float* __restrict__ w3,
    __half* __restrict__ out)
{
    int i = blockIdx.x * 256 + threadIdx.x;
    const float* src; int off;
    if (i < 196608)      { src = w0; off = i; }
    else if (i < 262144) { src = w1; off = i - 196608; }
    else if (i < 524288) { src = w2; off = i - 262144; }
    else                 { src = w3; off = i - 524288; }
    float4 v = ((const float4*)src)[off];
    ((__half2*)out)[2 * i]     = __floats2half2_rn(v.x, v.y);
    ((__half2*)out)[2 * i + 1] = __floats2half2_rn(v.z, v.w);
}

// ---------------------------------------------------------------------------
// LayerNorm (LN1): fp32 in -> fp16 out
// ---------------------------------------------------------------------------
__global__ __launch_bounds__(128) void ln_kernel_h(
    const float* __restrict__ x, const float* __restrict__ w,
    const float* __restrict__ b, __half* __restrict__ out)
{
    int row = blockIdx.x;
    int tid = threadIdx.x;
    const float4* xr = (const float4*)(x + (size_t)row * C_DIM);
    float4 v = xr[tid];
    float s  = v.x + v.y + v.z + v.w;
    float sq = v.x*v.x + v.y*v.y + v.z*v.z + v.w*v.w;
    #pragma unroll
    for (int o = 16; o > 0; o >>= 1) {
        s  += __shfl_xor_sync(0xffffffffu, s,  o);
        sq += __shfl_xor_sync(0xffffffffu, sq, o);
    }
    __shared__ float ss[4], ssq[4];
    if ((tid & 31) == 0) { ss[tid >> 5] = s; ssq[tid >> 5] = sq; }
    __syncthreads();
    s  = ss[0]  + ss[1]  + ss[2]  + ss[3];
    sq = ssq[0] + ssq[1] + ssq[2] + ssq[3];
    float mu  = s * (1.0f / C_DIM);
    float var = sq * (1.0f / C_DIM) - mu * mu;
    float inv = rsqrtf(var + 1e-5f);
    float4 wv = ((const float4*)w)[tid];
    float4 bv = ((const float4*)b)[tid];
    float o0 = (v.x - mu) * inv * wv.x + bv.x;
    float o1 = (v.y - mu) * inv * wv.y + bv.y;
    float o2 = (v.z - mu) * inv * wv.z + bv.z;
    float o3 = (v.w - mu) * inv * wv.w + bv.w;
    __half2* po = (__half2*)(out + (size_t)row * C_DIM);
    po[tid * 2]     = __floats2half2_rn(o0, o1);
    po[tid * 2 + 1] = __floats2half2_rn(o2, o3);
}

// ---------------------------------------------------------------------------
// HGEMM (R9-proven): BM=128, BN=128, BK=32, 3-stage cp.async, ldmatrix
// ---------------------------------------------------------------------------
template<int SPLITK, bool GELU>
__global__ __launch_bounds__(256, 2) void hgemm(
    const __half* __restrict__ A, const __half* __restrict__ B,
    const float* __restrict__ bias, void* __restrict__ Cout,
    int M, int N, int K)
{
    constexpr int BM = 128, BK = 32, ST = 3;
    constexpr int SK = 40;
    constexpr int A_BYTES = BM * SK * 2;
    constexpr int STAGE_BYTES = 2 * A_BYTES;

    extern __shared__ __align__(16) __half hsm[];
    const uint32_t sbase = (uint32_t)__cvta_generic_to_shared(hsm);

    const int tid  = threadIdx.x;
    const int wid  = tid >> 5;
    const int lane = tid & 31;
    const int g    = lane >> 2;
    const int tg   = lane & 3;
    const int warp_m = wid & 1;
    const int warp_n = wid >> 1;

    const int Kl = K / SPLITK;
    const int z  = (SPLITK > 1) ? blockIdx.z : 0;
    const __half* Ab = A + (size_t)blockIdx.y * BM * K + (size_t)z * Kl;
    const __half* Bb = B + (size_t)blockIdx.x * 128 * K + (size_t)z * Kl;

    float acc[4][4][4];
    #pragma unroll
    for (int mt = 0; mt < 4; mt++)
        #pragma unroll
        for (int nt = 0; nt < 4; nt++)
            #pragma unroll
            for (int i = 0; i < 4; i++) acc[mt][nt][i] = 0.0f;

    const int qh = lane >> 3, rh = lane & 7;
    const uint32_t a_lane =
        (uint32_t)(((warp_m * 64 + rh + 8 * (qh & 1)) * SK + (qh >> 1) * 8) * 2);
    const uint32_t b_lane =
        (uint32_t)(((warp_n * 32 + rh + 8 * (qh & 1)) * SK + (qh >> 1) * 8) * 2)
        + A_BYTES;

    auto load_chunk = [&](int buf, int k0) {
        uint32_t base = sbase + buf * STAGE_BYTES;
        #pragma unroll
        for (int it = 0; it < 2; ++it) {
            int i = tid + it * 256;
            int r = i >> 2, seg = i & 3;
            uint32_t so = (uint32_t)(r * SK + seg * 8) * 2;
            cp_async16_s(base + so,           Ab + (size_t)r * K + k0 + seg * 8);
            cp_async16_s(base + A_BYTES + so, Bb + (size_t)r * K + k0 + seg * 8);
        }
    };

    const int nch = Kl / BK;
    load_chunk(0, 0);
    asm volatile("cp.async.commit_group;");
    load_chunk(1, BK);
    asm volatile("cp.async.commit_group;");

    for (int c = 0; c < nch; ++c) {
        asm volatile("cp.async.wait_group 1;");
        __syncthreads();

        if (c + 2 < nch) load_chunk((c + 2) % ST, (c + 2) * BK);
        asm volatile("cp.async.commit_group;");

        const uint32_t st = sbase + (c % ST) * STAGE_BYTES;
        #pragma unroll
        for (int ks = 0; ks < 2; ++ks) {
            uint32_t aw[4][4], bw[4][2];
            #pragma unroll
            for (int nb = 0; nb < 2; ++nb) {
                uint32_t x0, x1, x2, x3;
                ldsm4(x0, x1, x2, x3, st + b_lane + nb * 1280 + ks * 32);
                bw[nb * 2][0] = x0; bw[nb * 2 + 1][0] = x1;
                bw[nb * 2][1] = x2; bw[nb * 2 + 1][1] = x3;
            }
            #pragma unroll
            for (int mt = 0; mt < 4; ++mt)
                ldsm4(aw[mt][0], aw[mt][1], aw[mt][2], aw[mt][3],
                      st + a_lane + mt * 1280 + ks * 32);
            #pragma unroll
            for (int mt = 0; mt < 4; ++mt)
                #pragma unroll
                for (int nt = 0; nt < 4; ++nt)
                    mma_f16(acc[mt][nt], aw[mt], bw[nt]);
        }
    }

    const int row_base = blockIdx.y * BM + warp_m * 64;
    const int col_base = blockIdx.x * 128 + warp_n * 32;

    if (SPLITK == 1) {
        __half* Ch = (__half*)Cout;
        #pragma unroll
        for (int mt = 0; mt < 4; ++mt) {
            #pragma unroll
            for (int nt = 0; nt < 4; ++nt) {
                int r0 = row_base + mt * 16 + g;
                int c0 = col_base + nt * 8 + 2 * tg;
                float b0 = bias[c0], b1 = bias[c0 + 1];
                #pragma unroll
                for (int hh = 0; hh < 2; ++hh) {
                    int r = r0 + hh * 8;
                    float v0 = acc[mt][nt][hh * 2 + 0] + b0;
                    float v1 = acc[mt][nt][hh * 2 + 1] + b1;
                    if (GELU) {
                        v0 = 0.5f * v0 * (1.0f + erff(v0 * 0.70710678118654752f));
                        v1 = 0.5f * v1 * (1.0f + erff(v1 * 0.70710678118654752f));
                    }
                    *(__half2*)(Ch + (size_t)r * N + c0) = __floats2half2_rn(v0, v1);
                }
            }
        }
    } else {
        float* Cp = (float*)Cout + (size_t)z * M * N;
        #pragma unroll
        for (int mt = 0; mt < 4; ++mt) {
            #pragma unroll
            for (int nt = 0; nt < 4; ++nt) {
                int r0 = row_base + mt * 16 + g;
                int c0 = col_base + nt * 8 + 2 * tg;
                #pragma unroll
                for (int hh = 0; hh < 2; ++hh) {
                    int r = r0 + hh * 8;
                    float2 ov;
                    ov.x = acc[mt][nt][hh * 2 + 0];
                    ov.y = acc[mt][nt][hh * 2 + 1];
                    *(float2*)(Cp + (size_t)r * N + c0) = ov;
                }
            }
        }
    }
}

// ---------------------------------------------------------------------------
// fc2 combine
// ---------------------------------------------------------------------------
__global__ __launch_bounds__(256) void sk_combine(
    const float* __restrict__ part, const float* __restrict__ bias,
    const float* __restrict__ res, float* __restrict__ out, int total4)
{
    int i = blockIdx.x * 256 + threadIdx.x;
    if (i >= total4) return;
    int col = (i << 2) & (C_DIM - 1);
    float4 p0 = ((const float4*)part)[i];
    float4 p1 = ((const float4*)part)[i + (M_ROWS * C_DIM / 4)];
    float4 bv = *(const float4*)(bias + col);
    float4 rv = ((const float4*)res)[i];
    float4 o;
    o.x = p0.x + p1.x + bv.x + rv.x;
    o.y = p0.y + p1.y + bv.y + rv.y;
    o.z = p0.z + p1.z + bv.z + rv.z;
    o.w = p0.w + p1.w + bv.w + rv.w;
    ((float4*)out)[i] = o;
}

// ---------------------------------------------------------------------------
// proj combine + LN2 fused
// ---------------------------------------------------------------------------
__global__ __launch_bounds__(128) void combine_ln(
    const float* __restrict__ part, const float* __restrict__ bias,
    const float* __restrict__ res, const float* __restrict__ w,
    const float* __restrict__ b, float* __restrict__ x2,
    __half* __restrict__ h)
{
    int row = blockIdx.x;
    int tid = threadIdx.x;
    size_t idx = (size_t)row * (C_DIM / 4) + tid;
    float4 p0 = ((const float4*)part)[idx];
    float4 p1 = ((const float4*)part)[idx + (M_ROWS * C_DIM / 4)];
    float4 bv = ((const float4*)bias)[tid];
    float4 rv = ((const float4*)res)[idx];
    float4 v;
    v.x = p0.x + p1.x + bv.x + rv.x;
    v.y = p0.y + p1.y + bv.y + rv.y;
    v.z = p0.z + p1.z + bv.z + rv.z;
    v.w = p0.w + p1.w + bv.w + rv.w;
    ((float4*)x2)[idx] = v;

    float s  = v.x + v.y + v.z + v.w;
    float sq = v.x*v.x + v.y*v.y + v.z*v.z + v.w*v.w;
    #pragma unroll
    for (int o = 16; o > 0; o >>= 1) {
        s  += __shfl_xor_sync(0xffffffffu, s,  o);
        sq += __shfl_xor_sync(0xffffffffu, sq, o);
    }
    __shared__ float ss[4], ssq[4];
    if ((tid & 31) == 0) { ss[tid >> 5] = s; ssq[tid >> 5] = sq; }
    __syncthreads();
    s  = ss[0]  + ss[1]  + ss[2]  + ss[3];
    sq = ssq[0] + ssq[1] + ssq[2] + ssq[3];
    float mu  = s * (1.0f / C_DIM);
    float var = sq * (1.0f / C_DIM) - mu * mu;
    float inv = rsqrtf(var + 1e-5f);
    float4 wv = ((const float4*)w)[tid];
    float4 bb = ((const float4*)b)[tid];
    float o0 = (v.x - mu) * inv * wv.x + bb.x;
    float o1 = (v.y - mu) * inv * wv.y + bb.y;
    float o2 = (v.z - mu) * inv * wv.z + bb.z;
    float o3 = (v.w - mu) * inv * wv.w + bb.w;
    __half2* ph = (__half2*)h;
    ph[idx * 2]     = __floats2half2_rn(o0, o1);
    ph[idx * 2 + 1] = __floats2half2_rn(o2, o3);
}

// ---------------------------------------------------------------------------
// Flash windowed attention (tensor cores).
// Block = 128 tokens x 1 head. 256 threads = 8 warps; warp w owns 16 rows.
// S[16 x 80-band] = Q @ K^T (mma), masked softmax in regs, O = P @ V (mma).
// ---------------------------------------------------------------------------
__global__ __launch_bounds__(256, 2) void fattn_kernel(
    const __half* __restrict__ qkv, const float* __restrict__ rel_bias,
    __half* __restrict__ out, int T)
{
    const int t0 = blockIdx.x * FA_TOK;
    const int h  = blockIdx.y;
    const int n  = blockIdx.z;
    const int tid  = threadIdx.x;
    const int wid  = tid >> 5;
    const int lane = tid & 31;
    const int g    = lane >> 2;
    const int tg   = lane & 3;

    extern __shared__ __align__(16) __half fsm[];
    __half* sQ = fsm;                              // [128][72]
    __half* sK = sQ + FA_TOK * FA_STR;             // [192][72]
    __half* sV = sK + FA_SPAN * FA_STR;            // [192][72]
    float*  sbias = (float*)(sV + FA_SPAN * FA_STR); // [64]
    const uint32_t sQb = (uint32_t)__cvta_generic_to_shared(sQ);
    const uint32_t sKb = (uint32_t)__cvta_generic_to_shared(sK);
    const uint32_t sVb = (uint32_t)__cvta_generic_to_shared(sV);

    // ---- fills ----
    if (tid < WIN) sbias[tid] = rel_bias[h * WIN + tid];
    const __half2 sc8 = __floats2half2_rn(0.125f, 0.125f);
    // Q: 128 rows x 8 segs, scaled
    for (int i = tid; i < FA_TOK * 8; i += 256) {
        int j = i >> 3, seg = i & 7;
        const __half2* src = (const __half2*)(qkv +
            ((size_t)n * T + t0 + j) * QKV_DIM + h * HEAD_D + seg * 8);
        __half2* dst = (__half2*)(sQ + j * FA_STR + seg * 8);
        #pragma unroll
        for (int u = 0; u < 4; ++u) dst[u] = __hmul2(src[u], sc8);
    }
    // K/V: 192 rows x 8 segs (rows >= 190 or invalid pos -> zero)
    for (int i = tid; i < FA_SPAN * 8; i += 256) {
        int j = i >> 3, seg = i & 7;
        int pos = t0 - LEFT + j;
        uint4 kv = make_uint4(0, 0, 0, 0), vv = make_uint4(0, 0, 0, 0);
        if (j < FA_REAL && pos >= 0 && pos < T) {
            const __half* base = qkv + ((size_t)n * T + pos) * QKV_DIM + h * HEAD_D;
            kv = *(const uint4*)(base + C_DIM + seg * 8);
            vv = *(const uint4*)(base + 2 * C_DIM + seg * 8);
        }
        *(uint4*)(sK + j * FA_STR + seg * 8) = kv;
        *(uint4*)(sV + j * FA_STR + seg * 8) = vv;
    }
    __syncthreads();

    const int r0 = wid * 16;     // warp's token rows [r0, r0+16); j0 = r0
    const int qh = lane >> 3, rh = lane & 7;

    // ---- S = Q @ K^T over the 80-wide band ----
    float acc[10][4];
    #pragma unroll
    for (int nt = 0; nt < 10; ++nt)
        #pragma unroll
        for (int c = 0; c < 4; ++c) acc[nt][c] = 0.0f;

    const uint32_t a_off = sQb +
        (uint32_t)(((r0 + rh + 8 * (qh & 1)) * FA_STR + (qh >> 1) * 8) * 2);
    const uint32_t b_off = sKb +
        (uint32_t)(((r0 + rh + 8 * (qh & 1)) * FA_STR + (qh >> 1) * 8) * 2);

    #pragma unroll
    for (int kc = 0; kc < 4; ++kc) {
        uint32_t aq[4];
        ldsm4(aq[0], aq[1], aq[2], aq[3], a_off + kc * 32);
        #pragma unroll
        for (int jp = 0; jp < 5; ++jp) {
            uint32_t x0, x1, x2, x3;
            ldsm4(x0, x1, x2, x3, b_off + (uint32_t)(jp * 16 * FA_STR * 2) + kc * 32);
            uint32_t bf0[2] = {x0, x2}, bf1[2] = {x1, x3};
            mma_f16(acc[jp * 2],     aq, bf0);
            mma_f16(acc[jp * 2 + 1], aq, bf1);
        }
    }

    // ---- masked softmax (unnormalized P in regs) ----
    float mx0 = -1e30f, mx1 = -1e30f;
    #pragma unroll
    for (int nt = 0; nt < 10; ++nt) {
        int jb = nt * 8 + 2 * tg;
        #pragma unroll
        for (int c = 0; c < 4; ++c) {
            int rl = g + ((c >> 1) << 3);
            int w  = jb + (c & 1) - rl;
            float s;
            if (w >= 0 && w < WIN) {
                int pos = t0 + r0 + rl - LEFT + w;
                s = acc[nt][c] + sbias[w];
                if (pos < 0 || pos >= T) s -= 100.0f;
            } else {
                s = -1e30f;
            }
            acc[nt][c] = s;
            if (c < 2) mx0 = fmaxf(mx0, s); else mx1 = fmaxf(mx1, s);
        }
    }
    mx0 = fmaxf(mx0, __shfl_xor_sync(0xffffffffu, mx0, 1));
    mx0 = fmaxf(mx0, __shfl_xor_sync(0xffffffffu, mx0, 2));
    mx1 = fmaxf(mx1, __shfl_xor_sync(0xffffffffu, mx1, 1));
    mx1 = fmaxf(mx1, __shfl_xor_sync(0xffffffffu, mx1, 2));

    float sm0 = 0.0f, sm1 = 0.0f;
    #pragma unroll
    for (int nt = 0; nt < 10; ++nt) {
        float e0 = __expf(acc[nt][0] - mx0);
        float e1 = __expf(acc[nt][1] - mx0);
        float e2 = __expf(acc[nt][2] - mx1);
        float e3 = __expf(acc[nt][3] - mx1);
        acc[nt][0] = e0; acc[nt][1] = e1; acc[nt][2] = e2; acc[nt][3] = e3;
        sm0 += e0 + e1; sm1 += e2 + e3;
    }
    sm0 += __shfl_xor_sync(0xffffffffu, sm0, 1);
    sm0 += __shfl_xor_sync(0xffffffffu, sm0, 2);
    sm1 += __shfl_xor_sync(0xffffffffu, sm1, 1);
    sm1 += __shfl_xor_sync(0xffffffffu, sm1, 2);
    const float rinv0 = 1.0f / sm0;
    const float rinv1 = 1.0f / sm1;

    // ---- O = P @ V ----
    float oacc[8][4];
    #pragma unroll
    for (int nt = 0; nt < 8; ++nt)
        #pragma unroll
        for (int c = 0; c < 4; ++c) oacc[nt][c] = 0.0f;

    // trans ldmatrix lane address: k-row = j0 + kc*16 + (lane&15), col = np*16 + 8*(lane>>4)
    const uint32_t v_off = sVb +
        (uint32_t)(((r0 + (lane & 15)) * FA_STR + 8 * (lane >> 4)) * 2);

    #pragma unroll
    for (int kc = 0; kc < 5; ++kc) {
        uint32_t ap[4];
        ap[0] = packh2(acc[2 * kc][0],     acc[2 * kc][1]);
        ap[1] = packh2(acc[2 * kc][2],     acc[2 * kc][3]);
        ap[2] = packh2(acc[2 * kc + 1][0], acc[2 * kc + 1][1]);
        ap[3] = packh2(acc[2 * kc + 1][2], acc[2 * kc + 1][3]);
        #pragma unroll
        for (int np = 0; np < 4; ++np) {
            uint32_t x0, x1, x2, x3;
            ldsm4t(x0, x1, x2, x3,
                   v_off + (uint32_t)(kc * 16 * FA_STR * 2) + (uint32_t)(np * 32));
            uint32_t bf0[2] = {x0, x1}, bf1[2] = {x2, x3};
            mma_f16(oacc[np * 2],     ap, bf0);
            mma_f16(oacc[np * 2 + 1], ap, bf1);
        }
    }

    // ---- scale + store ----
    __half* orow0 = out + ((size_t)n * T + t0 + r0 + g) * C_DIM + h * HEAD_D;
    __half* orow1 = orow0 + 8 * C_DIM;
    #pragma unroll
    for (int nt = 0; nt < 8; ++nt) {
        int d = nt * 8 + 2 * tg;
        *(__half2*)(orow0 + d) =
            __floats2half2_rn(oacc[nt][0] * rinv0, oacc[nt][1] * rinv0);
        *(__half2*)(orow1 + d) =
            __floats2half2_rn(oacc[nt][2] * rinv1, oacc[nt][3] * rinv1);
    }
}

// ---------------------------------------------------------------------------
// Launch
// ---------------------------------------------------------------------------
extern "C" void kernel_launch(void* const* d_in, const int* in_sizes, int n_in,
                              void* d_out, int out_size)
{
    const float* x       = (const float*)d_in[0];
    const float* norm1_w = (const float*)d_in[1];
    const float* norm1_b = (const float*)d_in[2];
    const float* qkv_w   = (const float*)d_in[3];
    const float* qkv_b   = (const float*)d_in[4];
    const float* relbias = (const float*)d_in[5];
    const float* proj_w  = (const float*)d_in[6];
    const float* proj_b  = (const float*)d_in[7];
    const float* norm2_w = (const float*)d_in[8];
    const float* norm2_b = (const float*)d_in[9];
    const float* fc1_w   = (const float*)d_in[10];
    const float* fc1_b   = (const float*)d_in[11];
    const float* fc2_w   = (const float*)d_in[12];
    const float* fc2_b   = (const float*)d_in[13];
    float* out = (float*)d_out;

    int M = in_sizes[0] / C_DIM;   // 4096
    int Nb = 2;
    int T = M / Nb;                // 2048

    __half *p_h16, *p_qkv16, *p_att16, *p_m1h, *p_w16;
    float *p_x2, *p_part;
    cudaGetSymbolAddress((void**)&p_h16,   g_h16);
    cudaGetSymbolAddress((void**)&p_qkv16, g_qkv16);
    cudaGetSymbolAddress((void**)&p_att16, g_att16);
    cudaGetSymbolAddress((void**)&p_x2,    g_x2);
    cudaGetSymbolAddress((void**)&p_m1h,   g_m1h);
    cudaGetSymbolAddress((void**)&p_part,  g_part);
    cudaGetSymbolAddress((void**)&p_w16,   g_w16);

    const int FA_SMEM = (FA_TOK + 2 * FA_SPAN) * FA_STR * 2 + 64 * 4; // 73984
    const int HG_SMEM = 3 * 20480;
    cudaFuncSetAttribute(fattn_kernel,
        cudaFuncAttributeMaxDynamicSharedMemorySize, FA_SMEM);
    cudaFuncSetAttribute(hgemm<1, false>,
        cudaFuncAttributeMaxDynamicSharedMemorySize, HG_SMEM);
    cudaFuncSetAttribute(hgemm<1, true>,
        cudaFuncAttributeMaxDynamicSharedMemorySize, HG_SMEM);
    cudaFuncSetAttribute(hgemm<2, false>,
        cudaFuncAttributeMaxDynamicSharedMemorySize, HG_SMEM);

    const int total4 = M_ROWS * C_DIM / 4;
    const int cblocks = (total4 + 255) / 256;

    // 0) weights -> fp16
    wconv<<<3072, 256>>>(qkv_w, proj_w, fc1_w, fc2_w, p_w16);

    // 1) h = LN1(x) -> fp16
    ln_kernel_h<<<M, 128>>>(x, norm1_w, norm1_b, p_h16);

    // 2) qkv (fp16)
    hgemm<1, false><<<dim3(QKV_DIM / 128, M / 128), 256, HG_SMEM>>>(
        p_h16, p_w16 + W_QKV, qkv_b, p_qkv16, M, QKV_DIM, C_DIM);

    // 3) flash windowed attention (fp16)
    fattn_kernel<<<dim3(T / FA_TOK, 8, Nb), 256, FA_SMEM>>>(
        p_qkv16, relbias, p_att16, T);

    // 4) proj split-K + fused combine/LN2
    hgemm<2, false><<<dim3(C_DIM / 128, M / 128, 2), 256, HG_SMEM>>>(
        p_att16, p_w16 + W_PROJ, nullptr, p_part, M, C_DIM, C_DIM);
    combine_ln<<<M, 128>>>(p_part, proj_b, x, norm2_w, norm2_b, p_x2, p_h16);

    // 5) fc1 + GELU (fp16)
    hgemm<1, true><<<dim3(HID_DIM / 128, M / 128), 256, HG_SMEM>>>(
        p_h16, p_w16 + W_FC1, fc1_b, p_m1h, M, HID_DIM, C_DIM);

    // 6) fc2 split-K + combine
    hgemm<2, false><<<dim3(C_DIM / 128, M / 128, 2), 256, HG_SMEM>>>(
        p_m1h, p_w16 + W_FC2, nullptr, p_part, M, C_DIM, HID_DIM);
    sk_combine<<<cblocks, 256>>>(p_part, fc2_b, p_x2, out, total4);
}

// round 12
// speedup vs baseline: 2.2834x; 1.0557x over previous
#include <cuda_runtime.h>
#include <cuda_fp16.h>
#include <math.h>
#include <stdint.h>

// ---------------------------------------------------------------------------
// Shapes: x (N=2, T=2048, C=512), H=8, hd=64, WIN=63, LEFT=31, hid=2048
// ---------------------------------------------------------------------------
#define C_DIM   512
#define HID_DIM 2048
#define QKV_DIM 1536
#define HEAD_D  64
#define WIN     63
#define LEFT    31
#define M_ROWS  4096

// fp16 weight buffer offsets (halves)
#define W_QKV  0
#define W_PROJ 786432
#define W_FC1  1048576
#define W_FC2  2097152
#define W_TOT  3145728

// flash-attention tiling
#define FA_TOK  128
#define FA_SPAN 192
#define FA_REAL (FA_TOK + WIN - 1)  // 190
#define FA_STR  72

// ---------------------------------------------------------------------------
// Scratch
// ---------------------------------------------------------------------------
__device__ __half g_h16  [M_ROWS * C_DIM];
__device__ __half g_qkv16[M_ROWS * QKV_DIM];
__device__ __half g_att16[M_ROWS * C_DIM];
__device__ float  g_x2   [M_ROWS * C_DIM];
__device__ __half g_m1h  [M_ROWS * HID_DIM];
__device__ float  g_part [2 * M_ROWS * C_DIM];
__device__ __half g_w16  [W_TOT];

// ---------------------------------------------------------------------------
// PTX helpers
// ---------------------------------------------------------------------------
__device__ __forceinline__ void cp_async16_s(uint32_t s, const void* g) {
    asm volatile("cp.async.cg.shared.global [%0], [%1], 16;\n" :: "r"(s), "l"(g));
}
__device__ __forceinline__ void ldsm4(uint32_t& r0, uint32_t& r1,
                                      uint32_t& r2, uint32_t& r3, uint32_t addr) {
    asm volatile("ldmatrix.sync.aligned.m8n8.x4.shared.b16 {%0,%1,%2,%3}, [%4];"
        : "=r"(r0), "=r"(r1), "=r"(r2), "=r"(r3) : "r"(addr));
}
__device__ __forceinline__ void ldsm4t(uint32_t& r0, uint32_t& r1,
                                       uint32_t& r2, uint32_t& r3, uint32_t addr) {
    asm volatile("ldmatrix.sync.aligned.m8n8.x4.trans.shared.b16 {%0,%1,%2,%3}, [%4];"
        : "=r"(r0), "=r"(r1), "=r"(r2), "=r"(r3) : "r"(addr));
}
__device__ __forceinline__ void mma_f16(float* c, const uint32_t* a, const uint32_t* b) {
    asm volatile(
        "mma.sync.aligned.m16n8k16.row.col.f32.f16.f16.f32 "
        "{%0,%1,%2,%3}, {%4,%5,%6,%7}, {%8,%9}, {%0,%1,%2,%3};\n"
        : "+f"(c[0]), "+f"(c[1]), "+f"(c[2]), "+f"(c[3])
        : "r"(a[0]), "r"(a[1]), "r"(a[2]), "r"(a[3]), "r"(b[0]), "r"(b[1]));
}
__device__ __forceinline__ uint32_t packh2(float a, float b) {
    __half2 h = __floats2half2_rn(a, b);
    return *reinterpret_cast<uint32_t*>(&h);
}

// ---------------------------------------------------------------------------
// prep: fused weight fp32->fp16 conversion (blocks 0..6143) + LN1 (rest)
// ---------------------------------------------------------------------------
__global__ __launch_bounds__(128) void prep(
    const float* __restrict__ w0, const float* __restrict__ w1,
    const float* __restrict__ w2, const float* __restrict__ w3,
    __half* __restrict__ wout,
    const float* __restrict__ x, const float* __restrict__ lw,
    const float* __restrict__ lb, __half* __restrict__ hout)
{
    if (blockIdx.x < 6144) {
        int i = blockIdx.x * 128 + threadIdx.x;   // float4 idx < 786432
        const float* src; int off;
        if (i < 196608)      { src = w0; off = i; }
        else if (i < 262144) { src = w1; off = i - 196608; }
        else if (i < 524288) { src = w2; off = i - 262144; }
        else                 { src = w3; off = i - 524288; }
        float4 v = ((const float4*)src)[off];
        ((__half2*)wout)[2 * i]     = __floats2half2_rn(v.x, v.y);
        ((__half2*)wout)[2 * i + 1] = __floats2half2_rn(v.z, v.w);
        return;
    }
    int row = blockIdx.x - 6144;
    int tid = threadIdx.x;
    const float4* xr = (const float4*)(x + (size_t)row * C_DIM);
    float4 v = xr[tid];
    float s  = v.x + v.y + v.z + v.w;
    float sq = v.x*v.x + v.y*v.y + v.z*v.z + v.w*v.w;
    #pragma unroll
    for (int o = 16; o > 0; o >>= 1) {
        s  += __shfl_xor_sync(0xffffffffu, s,  o);
        sq += __shfl_xor_sync(0xffffffffu, sq, o);
    }
    __shared__ float ss[4], ssq[4];
    if ((tid & 31) == 0) { ss[tid >> 5] = s; ssq[tid >> 5] = sq; }
    __syncthreads();
    s  = ss[0]  + ss[1]  + ss[2]  + ss[3];
    sq = ssq[0] + ssq[1] + ssq[2] + ssq[3];
    float mu  = s * (1.0f / C_DIM);
    float var = sq * (1.0f / C_DIM) - mu * mu;
    float inv = rsqrtf(var + 1e-5f);
    float4 wv = ((const float4*)lw)[tid];
    float4 bv = ((const float4*)lb)[tid];
    float o0 = (v.x - mu) * inv * wv.x + bv.x;
    float o1 = (v.y - mu) * inv * wv.y + bv.y;
    float o2 = (v.z - mu) * inv * wv.z + bv.z;
    float o3 = (v.w - mu) * inv * wv.w + bv.w;
    __half2* po = (__half2*)(hout + (size_t)row * C_DIM);
    po[tid * 2]     = __floats2half2_rn(o0, o1);
    po[tid * 2 + 1] = __floats2half2_rn(o2, o3);
}

// ---------------------------------------------------------------------------
// HGEMM: BM=128, BN=128, BK=64, 2-stage cp.async (single sync/chunk),
// ldmatrix fragments, (256,2).  SPLITK==1: +bias(+GELU) fp16 out.
// SPLITK==2: fp32 partials.
// ---------------------------------------------------------------------------
template<int SPLITK, bool GELU>
__global__ __launch_bounds__(256, 2) void hgemm(
    const __half* __restrict__ A, const __half* __restrict__ B,
    const float* __restrict__ bias, void* __restrict__ Cout,
    int M, int N, int K)
{
    constexpr int BM = 128, BK = 64;
    constexpr int SK = 72;                       // halves per smem row
    constexpr int A_BYTES = BM * SK * 2;         // 18432
    constexpr int STAGE_BYTES = 2 * A_BYTES;     // 36864
    constexpr int ROWSTEP = 16 * SK * 2;         // 2304 bytes per 16 rows

    extern __shared__ __align__(16) __half hsm[];
    const uint32_t sbase = (uint32_t)__cvta_generic_to_shared(hsm);

    const int tid  = threadIdx.x;
    const int wid  = tid >> 5;
    const int lane = tid & 31;
    const int g    = lane >> 2;
    const int tg   = lane & 3;
    const int warp_m = wid & 1;
    const int warp_n = wid >> 1;

    const int Kl = K / SPLITK;
    const int z  = (SPLITK > 1) ? blockIdx.z : 0;
    const __half* Ab = A + (size_t)blockIdx.y * BM * K + (size_t)z * Kl;
    const __half* Bb = B + (size_t)blockIdx.x * 128 * K + (size_t)z * Kl;

    float acc[4][4][4];
    #pragma unroll
    for (int mt = 0; mt < 4; mt++)
        #pragma unroll
        for (int nt = 0; nt < 4; nt++)
            #pragma unroll
            for (int i = 0; i < 4; i++) acc[mt][nt][i] = 0.0f;

    const int qh = lane >> 3, rh = lane & 7;
    const uint32_t a_lane =
        (uint32_t)(((warp_m * 64 + rh + 8 * (qh & 1)) * SK + (qh >> 1) * 8) * 2);
    const uint32_t b_lane =
        (uint32_t)(((warp_n * 32 + rh + 8 * (qh & 1)) * SK + (qh >> 1) * 8) * 2)
        + A_BYTES;

    // per chunk: A/B each 128 rows x 128B = 1024 x 16B; 4 per thread each
    auto load_chunk = [&](int buf, int k0) {
        uint32_t base = sbase + buf * STAGE_BYTES;
        #pragma unroll
        for (int it = 0; it < 4; ++it) {
            int i = tid + it * 256;
            int r = i >> 3, seg = i & 7;
            uint32_t so = (uint32_t)(r * SK + seg * 8) * 2;
            cp_async16_s(base + so,           Ab + (size_t)r * K + k0 + seg * 8);
            cp_async16_s(base + A_BYTES + so, Bb + (size_t)r * K + k0 + seg * 8);
        }
    };

    const int nch = Kl / BK;
    load_chunk(0, 0);
    asm volatile("cp.async.commit_group;");

    for (int c = 0; c < nch; ++c) {
        asm volatile("cp.async.wait_group 0;");
        __syncthreads();

        if (c + 1 < nch) {
            load_chunk((c + 1) & 1, (c + 1) * BK);
            asm volatile("cp.async.commit_group;");
        }

        const uint32_t st = sbase + (c & 1) * STAGE_BYTES;
        #pragma unroll
        for (int ks = 0; ks < 4; ++ks) {
            uint32_t aw[4][4], bw[4][2];
            #pragma unroll
            for (int nb = 0; nb < 2; ++nb) {
                uint32_t x0, x1, x2, x3;
                // fragment block covers 16 n-rows -> step is ONE ROWSTEP per nb
                ldsm4(x0, x1, x2, x3, st + b_lane + nb * ROWSTEP + ks * 32);
                bw[nb * 2][0] = x0; bw[nb * 2 + 1][0] = x1;
                bw[nb * 2][1] = x2; bw[nb * 2 + 1][1] = x3;
            }
            #pragma unroll
            for (int mt = 0; mt < 4; ++mt)
                ldsm4(aw[mt][0], aw[mt][1], aw[mt][2], aw[mt][3],
                      st + a_lane + mt * ROWSTEP + ks * 32);
            #pragma unroll
            for (int mt = 0; mt < 4; ++mt)
                #pragma unroll
                for (int nt = 0; nt < 4; ++nt)
                    mma_f16(acc[mt][nt], aw[mt], bw[nt]);
        }
    }

    const int row_base = blockIdx.y * BM + warp_m * 64;
    const int col_base = blockIdx.x * 128 + warp_n * 32;

    if (SPLITK == 1) {
        __half* Ch = (__half*)Cout;
        #pragma unroll
        for (int mt = 0; mt < 4; ++mt) {
            #pragma unroll
            for (int nt = 0; nt < 4; ++nt) {
                int r0 = row_base + mt * 16 + g;
                int c0 = col_base + nt * 8 + 2 * tg;
                float b0 = bias[c0], b1 = bias[c0 + 1];
                #pragma unroll
                for (int hh = 0; hh < 2; ++hh) {
                    int r = r0 + hh * 8;
                    float v0 = acc[mt][nt][hh * 2 + 0] + b0;
                    float v1 = acc[mt][nt][hh * 2 + 1] + b1;
                    if (GELU) {
                        v0 = 0.5f * v0 * (1.0f + erff(v0 * 0.70710678118654752f));
                        v1 = 0.5f * v1 * (1.0f + erff(v1 * 0.70710678118654752f));
                    }
                    *(__half2*)(Ch + (size_t)r * N + c0) = __floats2half2_rn(v0, v1);
                }
            }
        }
    } else {
        float* Cp = (float*)Cout + (size_t)z * M * N;
        #pragma unroll
        for (int mt = 0; mt < 4; ++mt) {
            #pragma unroll
            for (int nt = 0; nt < 4; ++nt) {
                int r0 = row_base + mt * 16 + g;
                int c0 = col_base + nt * 8 + 2 * tg;
                #pragma unroll
                for (int hh = 0; hh < 2; ++hh) {
                    int r = r0 + hh * 8;
                    float2 ov;
                    ov.x = acc[mt][nt][hh * 2 + 0];
                    ov.y = acc[mt][nt][hh * 2 + 1];
                    *(float2*)(Cp + (size_t)r * N + c0) = ov;
                }
            }
        }
    }
}

// ---------------------------------------------------------------------------
// fc2 combine
// ---------------------------------------------------------------------------
__global__ __launch_bounds__(256) void sk_combine(
    const float* __restrict__ part, const float* __restrict__ bias,
    const float* __restrict__ res, float* __restrict__ out, int total4)
{
    int i = blockIdx.x * 256 + threadIdx.x;
    if (i >= total4) return;
    int col = (i << 2) & (C_DIM - 1);
    float4 p0 = ((const float4*)part)[i];
    float4 p1 = ((const float4*)part)[i + (M_ROWS * C_DIM / 4)];
    float4 bv = *(const float4*)(bias + col);
    float4 rv = ((const float4*)res)[i];
    float4 o;
    o.x = p0.x + p1.x + bv.x + rv.x;
    o.y = p0.y + p1.y + bv.y + rv.y;
    o.z = p0.z + p1.z + bv.z + rv.z;
    o.w = p0.w + p1.w + bv.w + rv.w;
    ((float4*)out)[i] = o;
}

// ---------------------------------------------------------------------------
// proj combine + LN2 fused
// ---------------------------------------------------------------------------
__global__ __launch_bounds__(128) void combine_ln(
    const float* __restrict__ part, const float* __restrict__ bias,
    const float* __restrict__ res, const float* __restrict__ w,
    const float* __restrict__ b, float* __restrict__ x2,
    __half* __restrict__ h)
{
    int row = blockIdx.x;
    int tid = threadIdx.x;
    size_t idx = (size_t)row * (C_DIM / 4) + tid;
    float4 p0 = ((const float4*)part)[idx];
    float4 p1 = ((const float4*)part)[idx + (M_ROWS * C_DIM / 4)];
    float4 bv = ((const float4*)bias)[tid];
    float4 rv = ((const float4*)res)[idx];
    float4 v;
    v.x = p0.x + p1.x + bv.x + rv.x;
    v.y = p0.y + p1.y + bv.y + rv.y;
    v.z = p0.z + p1.z + bv.z + rv.z;
    v.w = p0.w + p1.w + bv.w + rv.w;
    ((float4*)x2)[idx] = v;

    float s  = v.x + v.y + v.z + v.w;
    float sq = v.x*v.x + v.y*v.y + v.z*v.z + v.w*v.w;
    #pragma unroll
    for (int o = 16; o > 0; o >>= 1) {
        s  += __shfl_xor_sync(0xffffffffu, s,  o);
        sq += __shfl_xor_sync(0xffffffffu, sq, o);
    }
    __shared__ float ss[4], ssq[4];
    if ((tid & 31) == 0) { ss[tid >> 5] = s; ssq[tid >> 5] = sq; }
    __syncthreads();
    s  = ss[0]  + ss[1]  + ss[2]  + ss[3];
    sq = ssq[0] + ssq[1] + ssq[2] + ssq[3];
    float mu  = s * (1.0f / C_DIM);
    float var = sq * (1.0f / C_DIM) - mu * mu;
    float inv = rsqrtf(var + 1e-5f);
    float4 wv = ((const float4*)w)[tid];
    float4 bb = ((const float4*)b)[tid];
    float o0 = (v.x - mu) * inv * wv.x + bb.x;
    float o1 = (v.y - mu) * inv * wv.y + bb.y;
    float o2 = (v.z - mu) * inv * wv.z + bb.z;
    float o3 = (v.w - mu) * inv * wv.w + bb.w;
    __half2* ph = (__half2*)h;
    ph[idx * 2]     = __floats2half2_rn(o0, o1);
    ph[idx * 2 + 1] = __floats2half2_rn(o2, o3);
}

// ---------------------------------------------------------------------------
// Flash windowed attention (R10-proven)
// ---------------------------------------------------------------------------
__global__ __launch_bounds__(256, 2) void fattn_kernel(
    const __half* __restrict__ qkv, const float* __restrict__ rel_bias,
    __half* __restrict__ out, int T)
{
    const int t0 = blockIdx.x * FA_TOK;
    const int h  = blockIdx.y;
    const int n  = blockIdx.z;
    const int tid  = threadIdx.x;
    const int wid  = tid >> 5;
    const int lane = tid & 31;
    const int g    = lane >> 2;
    const int tg   = lane & 3;

    extern __shared__ __align__(16) __half fsm[];
    __half* sQ = fsm;
    __half* sK = sQ + FA_TOK * FA_STR;
    __half* sV = sK + FA_SPAN * FA_STR;
    float*  sbias = (float*)(sV + FA_SPAN * FA_STR);
    const uint32_t sQb = (uint32_t)__cvta_generic_to_shared(sQ);
    const uint32_t sKb = (uint32_t)__cvta_generic_to_shared(sK);
    const uint32_t sVb = (uint32_t)__cvta_generic_to_shared(sV);

    if (tid < WIN) sbias[tid] = rel_bias[h * WIN + tid];
    const __half2 sc8 = __floats2half2_rn(0.125f, 0.125f);
    for (int i = tid; i < FA_TOK * 8; i += 256) {
        int j = i >> 3, seg = i & 7;
        const __half2* src = (const __half2*)(qkv +
            ((size_t)n * T + t0 + j) * QKV_DIM + h * HEAD_D + seg * 8);
        __half2* dst = (__half2*)(sQ + j * FA_STR + seg * 8);
        #pragma unroll
        for (int u = 0; u < 4; ++u) dst[u] = __hmul2(src[u], sc8);
    }
    for (int i = tid; i < FA_SPAN * 8; i += 256) {
        int j = i >> 3, seg = i & 7;
        int pos = t0 - LEFT + j;
        uint4 kv = make_uint4(0, 0, 0, 0), vv = make_uint4(0, 0, 0, 0);
        if (j < FA_REAL && pos >= 0 && pos < T) {
            const __half* base = qkv + ((size_t)n * T + pos) * QKV_DIM + h * HEAD_D;
            kv = *(const uint4*)(base + C_DIM + seg * 8);
            vv = *(const uint4*)(base + 2 * C_DIM + seg * 8);
        }
        *(uint4*)(sK + j * FA_STR + seg * 8) = kv;
        *(uint4*)(sV + j * FA_STR + seg * 8) = vv;
    }
    __syncthreads();

    const int r0 = wid * 16;
    const int qh = lane >> 3, rh = lane & 7;

    float acc[10][4];
    #pragma unroll
    for (int nt = 0; nt < 10; ++nt)
        #pragma unroll
        for (int c = 0; c < 4; ++c) acc[nt][c] = 0.0f;

    const uint32_t a_off = sQb +
        (uint32_t)(((r0 + rh + 8 * (qh & 1)) * FA_STR + (qh >> 1) * 8) * 2);
    const uint32_t b_off = sKb +
        (uint32_t)(((r0 + rh + 8 * (qh & 1)) * FA_STR + (qh >> 1) * 8) * 2);

    #pragma unroll
    for (int kc = 0; kc < 4; ++kc) {
        uint32_t aq[4];
        ldsm4(aq[0], aq[1], aq[2], aq[3], a_off + kc * 32);
        #pragma unroll
        for (int jp = 0; jp < 5; ++jp) {
            uint32_t x0, x1, x2, x3;
            ldsm4(x0, x1, x2, x3, b_off + (uint32_t)(jp * 16 * FA_STR * 2) + kc * 32);
            uint32_t bf0[2] = {x0, x2}, bf1[2] = {x1, x3};
            mma_f16(acc[jp * 2],     aq, bf0);
            mma_f16(acc[jp * 2 + 1], aq, bf1);
        }
    }

    float mx0 = -1e30f, mx1 = -1e30f;
    #pragma unroll
    for (int nt = 0; nt < 10; ++nt) {
        int jb = nt * 8 + 2 * tg;
        #pragma unroll
        for (int c = 0; c < 4; ++c) {
            int rl = g + ((c >> 1) << 3);
            int w  = jb + (c & 1) - rl;
            float s;
            if (w >= 0 && w < WIN) {
                int pos = t0 + r0 + rl - LEFT + w;
                s = acc[nt][c] + sbias[w];
                if (pos < 0 || pos >= T) s -= 100.0f;
            } else {
                s = -1e30f;
            }
            acc[nt][c] = s;
            if (c < 2) mx0 = fmaxf(mx0, s); else mx1 = fmaxf(mx1, s);
        }
    }
    mx0 = fmaxf(mx0, __shfl_xor_sync(0xffffffffu, mx0, 1));
    mx0 = fmaxf(mx0, __shfl_xor_sync(0xffffffffu, mx0, 2));
    mx1 = fmaxf(mx1, __shfl_xor_sync(0xffffffffu, mx1, 1));
    mx1 = fmaxf(mx1, __shfl_xor_sync(0xffffffffu, mx1, 2));

    float sm0 = 0.0f, sm1 = 0.0f;
    #pragma unroll
    for (int nt = 0; nt < 10; ++nt) {
        float e0 = __expf(acc[nt][0] - mx0);
        float e1 = __expf(acc[nt][1] - mx0);
        float e2 = __expf(acc[nt][2] - mx1);
        float e3 = __expf(acc[nt][3] - mx1);
        acc[nt][0] = e0; acc[nt][1] = e1; acc[nt][2] = e2; acc[nt][3] = e3;
        sm0 += e0 + e1; sm1 += e2 + e3;
    }
    sm0 += __shfl_xor_sync(0xffffffffu, sm0, 1);
    sm0 += __shfl_xor_sync(0xffffffffu, sm0, 2);
    sm1 += __shfl_xor_sync(0xffffffffu, sm1, 1);
    sm1 += __shfl_xor_sync(0xffffffffu, sm1, 2);
    const float rinv0 = 1.0f / sm0;
    const float rinv1 = 1.0f / sm1;

    float oacc[8][4];
    #pragma unroll
    for (int nt = 0; nt < 8; ++nt)
        #pragma unroll
        for (int c = 0; c < 4; ++c) oacc[nt][c] = 0.0f;

    const uint32_t v_off = sVb +
        (uint32_t)(((r0 + (lane & 15)) * FA_STR + 8 * (lane >> 4)) * 2);

    #pragma unroll
    for (int kc = 0; kc < 5; ++kc) {
        uint32_t ap[4];
        ap[0] = packh2(acc[2 * kc][0],     acc[2 * kc][1]);
        ap[1] = packh2(acc[2 * kc][2],     acc[2 * kc][3]);
        ap[2] = packh2(acc[2 * kc + 1][0], acc[2 * kc + 1][1]);
        ap[3] = packh2(acc[2 * kc + 1][2], acc[2 * kc + 1][3]);
        #pragma unroll
        for (int np = 0; np < 4; ++np) {
            uint32_t x0, x1, x2, x3;
            ldsm4t(x0, x1, x2, x3,
                   v_off + (uint32_t)(kc * 16 * FA_STR * 2) + (uint32_t)(np * 32));
            uint32_t bf0[2] = {x0, x1}, bf1[2] = {x2, x3};
            mma_f16(oacc[np * 2],     ap, bf0);
            mma_f16(oacc[np * 2 + 1], ap, bf1);
        }
    }

    __half* orow0 = out + ((size_t)n * T + t0 + r0 + g) * C_DIM + h * HEAD_D;
    __half* orow1 = orow0 + 8 * C_DIM;
    #pragma unroll
    for (int nt = 0; nt < 8; ++nt) {
        int d = nt * 8 + 2 * tg;
        *(__half2*)(orow0 + d) =
            __floats2half2_rn(oacc[nt][0] * rinv0, oacc[nt][1] * rinv0);
        *(__half2*)(orow1 + d) =
            __floats2half2_rn(oacc[nt][2] * rinv1, oacc[nt][3] * rinv1);
    }
}

// ---------------------------------------------------------------------------
// Launch
// ---------------------------------------------------------------------------
extern "C" void kernel_launch(void* const* d_in, const int* in_sizes, int n_in,
                              void* d_out, int out_size)
{
    const float* x       = (const float*)d_in[0];
    const float* norm1_w = (const float*)d_in[1];
    const float* norm1_b = (const float*)d_in[2];
    const float* qkv_w   = (const float*)d_in[3];
    const float* qkv_b   = (const float*)d_in[4];
    const float* relbias = (const float*)d_in[5];
    const float* proj_w  = (const float*)d_in[6];
    const float* proj_b  = (const float*)d_in[7];
    const float* norm2_w = (const float*)d_in[8];
    const float* norm2_b = (const float*)d_in[9];
    const float* fc1_w   = (const float*)d_in[10];
    const float* fc1_b   = (const float*)d_in[11];
    const float* fc2_w   = (const float*)d_in[12];
    const float* fc2_b   = (const float*)d_in[13];
    float* out = (float*)d_out;

    int M = in_sizes[0] / C_DIM;   // 4096
    int Nb = 2;
    int T = M / Nb;                // 2048

    __half *p_h16, *p_qkv16, *p_att16, *p_m1h, *p_w16;
    float *p_x2, *p_part;
    cudaGetSymbolAddress((void**)&p_h16,   g_h16);
    cudaGetSymbolAddress((void**)&p_qkv16, g_qkv16);
    cudaGetSymbolAddress((void**)&p_att16, g_att16);
    cudaGetSymbolAddress((void**)&p_x2,    g_x2);
    cudaGetSymbolAddress((void**)&p_m1h,   g_m1h);
    cudaGetSymbolAddress((void**)&p_part,  g_part);
    cudaGetSymbolAddress((void**)&p_w16,   g_w16);

    const int FA_SMEM = (FA_TOK + 2 * FA_SPAN) * FA_STR * 2 + 64 * 4;
    const int HG_SMEM = 2 * 36864;   // 73728
    cudaFuncSetAttribute(fattn_kernel,
        cudaFuncAttributeMaxDynamicSharedMemorySize, FA_SMEM);
    cudaFuncSetAttribute(hgemm<1, false>,
        cudaFuncAttributeMaxDynamicSharedMemorySize, HG_SMEM);
    cudaFuncSetAttribute(hgemm<1, true>,
        cudaFuncAttributeMaxDynamicSharedMemorySize, HG_SMEM);
    cudaFuncSetAttribute(hgemm<2, false>,
        cudaFuncAttributeMaxDynamicSharedMemorySize, HG_SMEM);

    const int total4 = M_ROWS * C_DIM / 4;
    const int cblocks = (total4 + 255) / 256;

    // 0+1) fused weights->fp16 and LN1
    prep<<<6144 + M, 128>>>(qkv_w, proj_w, fc1_w, fc2_w, p_w16,
                            x, norm1_w, norm1_b, p_h16);

    // 2) qkv (fp16)
    hgemm<1, false><<<dim3(QKV_DIM / 128, M / 128), 256, HG_SMEM>>>(
        p_h16, p_w16 + W_QKV, qkv_b, p_qkv16, M, QKV_DIM, C_DIM);

    // 3) flash windowed attention (fp16)
    fattn_kernel<<<dim3(T / FA_TOK, 8, Nb), 256, FA_SMEM>>>(
        p_qkv16, relbias, p_att16, T);

    // 4) proj split-K + fused combine/LN2
    hgemm<2, false><<<dim3(C_DIM / 128, M / 128, 2), 256, HG_SMEM>>>(
        p_att16, p_w16 + W_PROJ, nullptr, p_part, M, C_DIM, C_DIM);
    combine_ln<<<M, 128>>>(p_part, proj_b, x, norm2_w, norm2_b, p_x2, p_h16);

    // 5) fc1 + GELU (fp16)
    hgemm<1, true><<<dim3(HID_DIM / 128, M / 128), 256, HG_SMEM>>>(
        p_h16, p_w16 + W_FC1, fc1_b, p_m1h, M, HID_DIM, C_DIM);

    // 6) fc2 split-K + combine
    hgemm<2, false><<<dim3(C_DIM / 128, M / 128, 2), 256, HG_SMEM>>>(
        p_m1h, p_w16 + W_FC2, nullptr, p_part, M, C_DIM, HID_DIM);
    sk_combine<<<cblocks, 256>>>(p_part, fc2_b, p_x2, out, total4);
}

// round 13
// speedup vs baseline: 2.3036x; 1.0088x over previous
#include <cuda_runtime.h>
#include <cuda_fp16.h>
#include <math.h>
#include <stdint.h>

// ---------------------------------------------------------------------------
// Shapes: x (N=2, T=2048, C=512), H=8, hd=64, WIN=63, LEFT=31, hid=2048
// ---------------------------------------------------------------------------
#define C_DIM   512
#define HID_DIM 2048
#define QKV_DIM 1536
#define HEAD_D  64
#define WIN     63
#define LEFT    31
#define M_ROWS  4096

// fp16 weight buffer offsets (halves)
#define W_QKV  0
#define W_PROJ 786432
#define W_FC1  1048576
#define W_FC2  2097152
#define W_TOT  3145728

// flash-attention tiling
#define FA_TOK  128
#define FA_SPAN 192
#define FA_REAL (FA_TOK + WIN - 1)  // 190
#define FA_STR  72

// ---------------------------------------------------------------------------
// Scratch
// ---------------------------------------------------------------------------
__device__ __half g_h16  [M_ROWS * C_DIM];
__device__ __half g_qkv16[M_ROWS * QKV_DIM];
__device__ __half g_att16[M_ROWS * C_DIM];
__device__ float  g_x2   [M_ROWS * C_DIM];
__device__ __half g_m1h  [M_ROWS * HID_DIM];
__device__ __half g_w16  [W_TOT];

// ---------------------------------------------------------------------------
// PTX helpers
// ---------------------------------------------------------------------------
__device__ __forceinline__ void cp_async16_s(uint32_t s, const void* g) {
    asm volatile("cp.async.cg.shared.global [%0], [%1], 16;\n" :: "r"(s), "l"(g));
}
__device__ __forceinline__ void ldsm4(uint32_t& r0, uint32_t& r1,
                                      uint32_t& r2, uint32_t& r3, uint32_t addr) {
    asm volatile("ldmatrix.sync.aligned.m8n8.x4.shared.b16 {%0,%1,%2,%3}, [%4];"
        : "=r"(r0), "=r"(r1), "=r"(r2), "=r"(r3) : "r"(addr));
}
__device__ __forceinline__ void ldsm4t(uint32_t& r0, uint32_t& r1,
                                       uint32_t& r2, uint32_t& r3, uint32_t addr) {
    asm volatile("ldmatrix.sync.aligned.m8n8.x4.trans.shared.b16 {%0,%1,%2,%3}, [%4];"
        : "=r"(r0), "=r"(r1), "=r"(r2), "=r"(r3) : "r"(addr));
}
__device__ __forceinline__ void mma_f16(float* c, const uint32_t* a, const uint32_t* b) {
    asm volatile(
        "mma.sync.aligned.m16n8k16.row.col.f32.f16.f16.f32 "
        "{%0,%1,%2,%3}, {%4,%5,%6,%7}, {%8,%9}, {%0,%1,%2,%3};\n"
        : "+f"(c[0]), "+f"(c[1]), "+f"(c[2]), "+f"(c[3])
        : "r"(a[0]), "r"(a[1]), "r"(a[2]), "r"(a[3]), "r"(b[0]), "r"(b[1]));
}
__device__ __forceinline__ uint32_t packh2(float a, float b) {
    __half2 h = __floats2half2_rn(a, b);
    return *reinterpret_cast<uint32_t*>(&h);
}

// ---------------------------------------------------------------------------
// prep: fused weight fp32->fp16 conversion (blocks 0..6143) + LN1 (rest)
// ---------------------------------------------------------------------------
__global__ __launch_bounds__(128) void prep(
    const float* __restrict__ w0, const float* __restrict__ w1,
    const float* __restrict__ w2, const float* __restrict__ w3,
    __half* __restrict__ wout,
    const float* __restrict__ x, const float* __restrict__ lw,
    const float* __restrict__ lb, __half* __restrict__ hout)
{
    if (blockIdx.x < 6144) {
        int i = blockIdx.x * 128 + threadIdx.x;
        const float* src; int off;
        if (i < 196608)      { src = w0; off = i; }
        else if (i < 262144) { src = w1; off = i - 196608; }
        else if (i < 524288) { src = w2; off = i - 262144; }
        else                 { src = w3; off = i - 524288; }
        float4 v = ((const float4*)src)[off];
        ((__half2*)wout)[2 * i]     = __floats2half2_rn(v.x, v.y);
        ((__half2*)wout)[2 * i + 1] = __floats2half2_rn(v.z, v.w);
        return;
    }
    int row = blockIdx.x - 6144;
    int tid = threadIdx.x;
    const float4* xr = (const float4*)(x + (size_t)row * C_DIM);
    float4 v = xr[tid];
    float s  = v.x + v.y + v.z + v.w;
    float sq = v.x*v.x + v.y*v.y + v.z*v.z + v.w*v.w;
    #pragma unroll
    for (int o = 16; o > 0; o >>= 1) {
        s  += __shfl_xor_sync(0xffffffffu, s,  o);
        sq += __shfl_xor_sync(0xffffffffu, sq, o);
    }
    __shared__ float ss[4], ssq[4];
    if ((tid & 31) == 0) { ss[tid >> 5] = s; ssq[tid >> 5] = sq; }
    __syncthreads();
    s  = ss[0]  + ss[1]  + ss[2]  + ss[3];
    sq = ssq[0] + ssq[1] + ssq[2] + ssq[3];
    float mu  = s * (1.0f / C_DIM);
    float var = sq * (1.0f / C_DIM) - mu * mu;
    float inv = rsqrtf(var + 1e-5f);
    float4 wv = ((const float4*)lw)[tid];
    float4 bv = ((const float4*)lb)[tid];
    float o0 = (v.x - mu) * inv * wv.x + bv.x;
    float o1 = (v.y - mu) * inv * wv.y + bv.y;
    float o2 = (v.z - mu) * inv * wv.z + bv.z;
    float o3 = (v.w - mu) * inv * wv.w + bv.w;
    __half2* po = (__half2*)(hout + (size_t)row * C_DIM);
    po[tid * 2]     = __floats2half2_rn(o0, o1);
    po[tid * 2 + 1] = __floats2half2_rn(o2, o3);
}

// ---------------------------------------------------------------------------
// LN2: fp32 in -> fp16 out
// ---------------------------------------------------------------------------
__global__ __launch_bounds__(128) void ln_kernel_h(
    const float* __restrict__ x, const float* __restrict__ w,
    const float* __restrict__ b, __half* __restrict__ out)
{
    int row = blockIdx.x;
    int tid = threadIdx.x;
    const float4* xr = (const float4*)(x + (size_t)row * C_DIM);
    float4 v = xr[tid];
    float s  = v.x + v.y + v.z + v.w;
    float sq = v.x*v.x + v.y*v.y + v.z*v.z + v.w*v.w;
    #pragma unroll
    for (int o = 16; o > 0; o >>= 1) {
        s  += __shfl_xor_sync(0xffffffffu, s,  o);
        sq += __shfl_xor_sync(0xffffffffu, sq, o);
    }
    __shared__ float ss[4], ssq[4];
    if ((tid & 31) == 0) { ss[tid >> 5] = s; ssq[tid >> 5] = sq; }
    __syncthreads();
    s  = ss[0]  + ss[1]  + ss[2]  + ss[3];
    sq = ssq[0] + ssq[1] + ssq[2] + ssq[3];
    float mu  = s * (1.0f / C_DIM);
    float var = sq * (1.0f / C_DIM) - mu * mu;
    float inv = rsqrtf(var + 1e-5f);
    float4 wv = ((const float4*)w)[tid];
    float4 bv = ((const float4*)b)[tid];
    float o0 = (v.x - mu) * inv * wv.x + bv.x;
    float o1 = (v.y - mu) * inv * wv.y + bv.y;
    float o2 = (v.z - mu) * inv * wv.z + bv.z;
    float o3 = (v.w - mu) * inv * wv.w + bv.w;
    __half2* po = (__half2*)(out + (size_t)row * C_DIM);
    po[tid * 2]     = __floats2half2_rn(o0, o1);
    po[tid * 2 + 1] = __floats2half2_rn(o2, o3);
}

// ---------------------------------------------------------------------------
// HGEMM-128 (qkv, fc1): BM=128, BN=128, BK=64, 2-stage, (256,2).
// bias (+GELU), fp16 out.
// ---------------------------------------------------------------------------
template<bool GELU>
__global__ __launch_bounds__(256, 2) void hgemm(
    const __half* __restrict__ A, const __half* __restrict__ B,
    const float* __restrict__ bias, __half* __restrict__ Cout,
    int M, int N, int K)
{
    constexpr int BM = 128, BK = 64;
    constexpr int SK = 72;
    constexpr int A_BYTES = BM * SK * 2;         // 18432
    constexpr int STAGE_BYTES = 2 * A_BYTES;
    constexpr int ROWSTEP = 16 * SK * 2;

    extern __shared__ __align__(16) __half hsm[];
    const uint32_t sbase = (uint32_t)__cvta_generic_to_shared(hsm);

    const int tid  = threadIdx.x;
    const int wid  = tid >> 5;
    const int lane = tid & 31;
    const int g    = lane >> 2;
    const int tg   = lane & 3;
    const int warp_m = wid & 1;
    const int warp_n = wid >> 1;

    const __half* Ab = A + (size_t)blockIdx.y * BM * K;
    const __half* Bb = B + (size_t)blockIdx.x * 128 * K;

    float acc[4][4][4];
    #pragma unroll
    for (int mt = 0; mt < 4; mt++)
        #pragma unroll
        for (int nt = 0; nt < 4; nt++)
            #pragma unroll
            for (int i = 0; i < 4; i++) acc[mt][nt][i] = 0.0f;

    const int qh = lane >> 3, rh = lane & 7;
    const uint32_t a_lane =
        (uint32_t)(((warp_m * 64 + rh + 8 * (qh & 1)) * SK + (qh >> 1) * 8) * 2);
    const uint32_t b_lane =
        (uint32_t)(((warp_n * 32 + rh + 8 * (qh & 1)) * SK + (qh >> 1) * 8) * 2)
        + A_BYTES;

    auto load_chunk = [&](int buf, int k0) {
        uint32_t base = sbase + buf * STAGE_BYTES;
        #pragma unroll
        for (int it = 0; it < 4; ++it) {
            int i = tid + it * 256;
            int r = i >> 3, seg = i & 7;
            uint32_t so = (uint32_t)(r * SK + seg * 8) * 2;
            cp_async16_s(base + so,           Ab + (size_t)r * K + k0 + seg * 8);
            cp_async16_s(base + A_BYTES + so, Bb + (size_t)r * K + k0 + seg * 8);
        }
    };

    const int nch = K / BK;
    load_chunk(0, 0);
    asm volatile("cp.async.commit_group;");

    for (int c = 0; c < nch; ++c) {
        asm volatile("cp.async.wait_group 0;");
        __syncthreads();

        if (c + 1 < nch) {
            load_chunk((c + 1) & 1, (c + 1) * BK);
            asm volatile("cp.async.commit_group;");
        }

        const uint32_t st = sbase + (c & 1) * STAGE_BYTES;
        #pragma unroll
        for (int ks = 0; ks < 4; ++ks) {
            uint32_t aw[4][4], bw[4][2];
            #pragma unroll
            for (int nb = 0; nb < 2; ++nb) {
                uint32_t x0, x1, x2, x3;
                ldsm4(x0, x1, x2, x3, st + b_lane + nb * ROWSTEP + ks * 32);
                bw[nb * 2][0] = x0; bw[nb * 2 + 1][0] = x1;
                bw[nb * 2][1] = x2; bw[nb * 2 + 1][1] = x3;
            }
            #pragma unroll
            for (int mt = 0; mt < 4; ++mt)
                ldsm4(aw[mt][0], aw[mt][1], aw[mt][2], aw[mt][3],
                      st + a_lane + mt * ROWSTEP + ks * 32);
            #pragma unroll
            for (int mt = 0; mt < 4; ++mt)
                #pragma unroll
                for (int nt = 0; nt < 4; ++nt)
                    mma_f16(acc[mt][nt], aw[mt], bw[nt]);
        }
    }

    const int row_base = blockIdx.y * BM + warp_m * 64;
    const int col_base = blockIdx.x * 128 + warp_n * 32;
    #pragma unroll
    for (int mt = 0; mt < 4; ++mt) {
        #pragma unroll
        for (int nt = 0; nt < 4; ++nt) {
            int r0 = row_base + mt * 16 + g;
            int c0 = col_base + nt * 8 + 2 * tg;
            float b0 = bias[c0], b1 = bias[c0 + 1];
            #pragma unroll
            for (int hh = 0; hh < 2; ++hh) {
                int r = r0 + hh * 8;
                float v0 = acc[mt][nt][hh * 2 + 0] + b0;
                float v1 = acc[mt][nt][hh * 2 + 1] + b1;
                if (GELU) {
                    v0 = 0.5f * v0 * (1.0f + erff(v0 * 0.70710678118654752f));
                    v1 = 0.5f * v1 * (1.0f + erff(v1 * 0.70710678118654752f));
                }
                *(__half2*)(Cout + (size_t)r * N + c0) = __floats2half2_rn(v0, v1);
            }
        }
    }
}

// ---------------------------------------------------------------------------
// HGEMM-64 (proj, fc2): BM=64, BN=128, BK=64, 2-stage, (256,3).
// Epilogue: out(fp32) = acc + bias + res. No split-K, no partials.
// ---------------------------------------------------------------------------
__global__ __launch_bounds__(256, 3) void hgemm64(
    const __half* __restrict__ A, const __half* __restrict__ B,
    const float* __restrict__ bias, const float* __restrict__ res,
    float* __restrict__ Cout, int M, int N, int K)
{
    constexpr int BM = 64, BK = 64;
    constexpr int SK = 72;
    constexpr int A_BYTES = BM * SK * 2;         // 9216
    constexpr int B_BYTES = 128 * SK * 2;        // 18432
    constexpr int STAGE_BYTES = A_BYTES + B_BYTES;
    constexpr int ROWSTEP = 16 * SK * 2;

    extern __shared__ __align__(16) __half hsm[];
    const uint32_t sbase = (uint32_t)__cvta_generic_to_shared(hsm);

    const int tid  = threadIdx.x;
    const int wid  = tid >> 5;
    const int lane = tid & 31;
    const int g    = lane >> 2;
    const int tg   = lane & 3;
    const int warp_m = wid & 1;      // 32 rows
    const int warp_n = wid >> 1;     // 32 cols

    const __half* Ab = A + (size_t)blockIdx.y * BM * K;
    const __half* Bb = B + (size_t)blockIdx.x * 128 * K;

    float acc[2][4][4];
    #pragma unroll
    for (int mt = 0; mt < 2; mt++)
        #pragma unroll
        for (int nt = 0; nt < 4; nt++)
            #pragma unroll
            for (int i = 0; i < 4; i++) acc[mt][nt][i] = 0.0f;

    const int qh = lane >> 3, rh = lane & 7;
    const uint32_t a_lane =
        (uint32_t)(((warp_m * 32 + rh + 8 * (qh & 1)) * SK + (qh >> 1) * 8) * 2);
    const uint32_t b_lane =
        (uint32_t)(((warp_n * 32 + rh + 8 * (qh & 1)) * SK + (qh >> 1) * 8) * 2)
        + A_BYTES;

    // per chunk: A 64 rows x 8 segs = 512 (2/thread); B 128 rows = 1024 (4/thread)
    auto load_chunk = [&](int buf, int k0) {
        uint32_t base = sbase + buf * STAGE_BYTES;
        #pragma unroll
        for (int it = 0; it < 2; ++it) {
            int i = tid + it * 256;
            int r = i >> 3, seg = i & 7;
            uint32_t so = (uint32_t)(r * SK + seg * 8) * 2;
            cp_async16_s(base + so, Ab + (size_t)r * K + k0 + seg * 8);
        }
        #pragma unroll
        for (int it = 0; it < 4; ++it) {
            int i = tid + it * 256;
            int r = i >> 3, seg = i & 7;
            uint32_t so = (uint32_t)(r * SK + seg * 8) * 2;
            cp_async16_s(base + A_BYTES + so, Bb + (size_t)r * K + k0 + seg * 8);
        }
    };

    const int nch = K / BK;
    load_chunk(0, 0);
    asm volatile("cp.async.commit_group;");

    for (int c = 0; c < nch; ++c) {
        asm volatile("cp.async.wait_group 0;");
        __syncthreads();

        if (c + 1 < nch) {
            load_chunk((c + 1) & 1, (c + 1) * BK);
            asm volatile("cp.async.commit_group;");
        }

        const uint32_t st = sbase + (c & 1) * STAGE_BYTES;
        #pragma unroll
        for (int ks = 0; ks < 4; ++ks) {
            uint32_t aw[2][4], bw[4][2];
            #pragma unroll
            for (int nb = 0; nb < 2; ++nb) {
                uint32_t x0, x1, x2, x3;
                ldsm4(x0, x1, x2, x3, st + b_lane + nb * ROWSTEP + ks * 32);
                bw[nb * 2][0] = x0; bw[nb * 2 + 1][0] = x1;
                bw[nb * 2][1] = x2; bw[nb * 2 + 1][1] = x3;
            }
            #pragma unroll
            for (int mt = 0; mt < 2; ++mt)
                ldsm4(aw[mt][0], aw[mt][1], aw[mt][2], aw[mt][3],
                      st + a_lane + mt * ROWSTEP + ks * 32);
            #pragma unroll
            for (int mt = 0; mt < 2; ++mt)
                #pragma unroll
                for (int nt = 0; nt < 4; ++nt)
                    mma_f16(acc[mt][nt], aw[mt], bw[nt]);
        }
    }

    const int row_base = blockIdx.y * BM + warp_m * 32;
    const int col_base = blockIdx.x * 128 + warp_n * 32;
    #pragma unroll
    for (int mt = 0; mt < 2; ++mt) {
        #pragma unroll
        for (int nt = 0; nt < 4; ++nt) {
            int r0 = row_base + mt * 16 + g;
            int c0 = col_base + nt * 8 + 2 * tg;
            float b0 = bias[c0], b1 = bias[c0 + 1];
            #pragma unroll
            for (int hh = 0; hh < 2; ++hh) {
                int r = r0 + hh * 8;
                size_t off = (size_t)r * N + c0;
                float2 rv = *(const float2*)(res + off);
                float2 ov;
                ov.x = acc[mt][nt][hh * 2 + 0] + b0 + rv.x;
                ov.y = acc[mt][nt][hh * 2 + 1] + b1 + rv.y;
                *(float2*)(Cout + off) = ov;
            }
        }
    }
}

// ---------------------------------------------------------------------------
// Flash windowed attention (R10-proven)
// ---------------------------------------------------------------------------
__global__ __launch_bounds__(256, 2) void fattn_kernel(
    const __half* __restrict__ qkv, const float* __restrict__ rel_bias,
    __half* __restrict__ out, int T)
{
    const int t0 = blockIdx.x * FA_TOK;
    const int h  = blockIdx.y;
    const int n  = blockIdx.z;
    const int tid  = threadIdx.x;
    const int wid  = tid >> 5;
    const int lane = tid & 31;
    const int g    = lane >> 2;
    const int tg   = lane & 3;

    extern __shared__ __align__(16) __half fsm[];
    __half* sQ = fsm;
    __half* sK = sQ + FA_TOK * FA_STR;
    __half* sV = sK + FA_SPAN * FA_STR;
    float*  sbias = (float*)(sV + FA_SPAN * FA_STR);
    const uint32_t sQb = (uint32_t)__cvta_generic_to_shared(sQ);
    const uint32_t sKb = (uint32_t)__cvta_generic_to_shared(sK);
    const uint32_t sVb = (uint32_t)__cvta_generic_to_shared(sV);

    if (tid < WIN) sbias[tid] = rel_bias[h * WIN + tid];
    const __half2 sc8 = __floats2half2_rn(0.125f, 0.125f);
    for (int i = tid; i < FA_TOK * 8; i += 256) {
        int j = i >> 3, seg = i & 7;
        const __half2* src = (const __half2*)(qkv +
            ((size_t)n * T + t0 + j) * QKV_DIM + h * HEAD_D + seg * 8);
        __half2* dst = (__half2*)(sQ + j * FA_STR + seg * 8);
        #pragma unroll
        for (int u = 0; u < 4; ++u) dst[u] = __hmul2(src[u], sc8);
    }
    for (int i = tid; i < FA_SPAN * 8; i += 256) {
        int j = i >> 3, seg = i & 7;
        int pos = t0 - LEFT + j;
        uint4 kv = make_uint4(0, 0, 0, 0), vv = make_uint4(0, 0, 0, 0);
        if (j < FA_REAL && pos >= 0 && pos < T) {
            const __half* base = qkv + ((size_t)n * T + pos) * QKV_DIM + h * HEAD_D;
            kv = *(const uint4*)(base + C_DIM + seg * 8);
            vv = *(const uint4*)(base + 2 * C_DIM + seg * 8);
        }
        *(uint4*)(sK + j * FA_STR + seg * 8) = kv;
        *(uint4*)(sV + j * FA_STR + seg * 8) = vv;
    }
    __syncthreads();

    const int r0 = wid * 16;
    const int qh = lane >> 3, rh = lane & 7;

    float acc[10][4];
    #pragma unroll
    for (int nt = 0; nt < 10; ++nt)
        #pragma unroll
        for (int c = 0; c < 4; ++c) acc[nt][c] = 0.0f;

    const uint32_t a_off = sQb +
        (uint32_t)(((r0 + rh + 8 * (qh & 1)) * FA_STR + (qh >> 1) * 8) * 2);
    const uint32_t b_off = sKb +
        (uint32_t)(((r0 + rh + 8 * (qh & 1)) * FA_STR + (qh >> 1) * 8) * 2);

    #pragma unroll
    for (int kc = 0; kc < 4; ++kc) {
        uint32_t aq[4];
        ldsm4(aq[0], aq[1], aq[2], aq[3], a_off + kc * 32);
        #pragma unroll
        for (int jp = 0; jp < 5; ++jp) {
            uint32_t x0, x1, x2, x3;
            ldsm4(x0, x1, x2, x3, b_off + (uint32_t)(jp * 16 * FA_STR * 2) + kc * 32);
            uint32_t bf0[2] = {x0, x2}, bf1[2] = {x1, x3};
            mma_f16(acc[jp * 2],     aq, bf0);
            mma_f16(acc[jp * 2 + 1], aq, bf1);
        }
    }

    float mx0 = -1e30f, mx1 = -1e30f;
    #pragma unroll
    for (int nt = 0; nt < 10; ++nt) {
        int jb = nt * 8 + 2 * tg;
        #pragma unroll
        for (int c = 0; c < 4; ++c) {
            int rl = g + ((c >> 1) << 3);
            int w  = jb + (c & 1) - rl;
            float s;
            if (w >= 0 && w < WIN) {
                int pos = t0 + r0 + rl - LEFT + w;
                s = acc[nt][c] + sbias[w];
                if (pos < 0 || pos >= T) s -= 100.0f;
            } else {
                s = -1e30f;
            }
            acc[nt][c] = s;
            if (c < 2) mx0 = fmaxf(mx0, s); else mx1 = fmaxf(mx1, s);
        }
    }
    mx0 = fmaxf(mx0, __shfl_xor_sync(0xffffffffu, mx0, 1));
    mx0 = fmaxf(mx0, __shfl_xor_sync(0xffffffffu, mx0, 2));
    mx1 = fmaxf(mx1, __shfl_xor_sync(0xffffffffu, mx1, 1));
    mx1 = fmaxf(mx1, __shfl_xor_sync(0xffffffffu, mx1, 2));

    float sm0 = 0.0f, sm1 = 0.0f;
    #pragma unroll
    for (int nt = 0; nt < 10; ++nt) {
        float e0 = __expf(acc[nt][0] - mx0);
        float e1 = __expf(acc[nt][1] - mx0);
        float e2 = __expf(acc[nt][2] - mx1);
        float e3 = __expf(acc[nt][3] - mx1);
        acc[nt][0] = e0; acc[nt][1] = e1; acc[nt][2] = e2; acc[nt][3] = e3;
        sm0 += e0 + e1; sm1 += e2 + e3;
    }
    sm0 += __shfl_xor_sync(0xffffffffu, sm0, 1);
    sm0 += __shfl_xor_sync(0xffffffffu, sm0, 2);
    sm1 += __shfl_xor_sync(0xffffffffu, sm1, 1);
    sm1 += __shfl_xor_sync(0xffffffffu, sm1, 2);
    const float rinv0 = 1.0f / sm0;
    const float rinv1 = 1.0f / sm1;

    float oacc[8][4];
    #pragma unroll
    for (int nt = 0; nt < 8; ++nt)
        #pragma unroll
        for (int c = 0; c < 4; ++c) oacc[nt][c] = 0.0f;

    const uint32_t v_off = sVb +
        (uint32_t)(((r0 + (lane & 15)) * FA_STR + 8 * (lane >> 4)) * 2);

    #pragma unroll
    for (int kc = 0; kc < 5; ++kc) {
        uint32_t ap[4];
        ap[0] = packh2(acc[2 * kc][0],     acc[2 * kc][1]);
        ap[1] = packh2(acc[2 * kc][2],     acc[2 * kc][3]);
        ap[2] = packh2(acc[2 * kc + 1][0], acc[2 * kc + 1][1]);
        ap[3] = packh2(acc[2 * kc + 1][2], acc[2 * kc + 1][3]);
        #pragma unroll
        for (int np = 0; np < 4; ++np) {
            uint32_t x0, x1, x2, x3;
            ldsm4t(x0, x1, x2, x3,
                   v_off + (uint32_t)(kc * 16 * FA_STR * 2) + (uint32_t)(np * 32));
            uint32_t bf0[2] = {x0, x1}, bf1[2] = {x2, x3};
            mma_f16(oacc[np * 2],     ap, bf0);
            mma_f16(oacc[np * 2 + 1], ap, bf1);
        }
    }

    __half* orow0 = out + ((size_t)n * T + t0 + r0 + g) * C_DIM + h * HEAD_D;
    __half* orow1 = orow0 + 8 * C_DIM;
    #pragma unroll
    for (int nt = 0; nt < 8; ++nt) {
        int d = nt * 8 + 2 * tg;
        *(__half2*)(orow0 + d) =
            __floats2half2_rn(oacc[nt][0] * rinv0, oacc[nt][1] * rinv0);
        *(__half2*)(orow1 + d) =
            __floats2half2_rn(oacc[nt][2] * rinv1, oacc[nt][3] * rinv1);
    }
}

// ---------------------------------------------------------------------------
// Launch
// ---------------------------------------------------------------------------
extern "C" void kernel_launch(void* const* d_in, const int* in_sizes, int n_in,
                              void* d_out, int out_size)
{
    const float* x       = (const float*)d_in[0];
    const float* norm1_w = (const float*)d_in[1];
    const float* norm1_b = (const float*)d_in[2];
    const float* qkv_w   = (const float*)d_in[3];
    const float* qkv_b   = (const float*)d_in[4];
    const float* relbias = (const float*)d_in[5];
    const float* proj_w  = (const float*)d_in[6];
    const float* proj_b  = (const float*)d_in[7];
    const float* norm2_w = (const float*)d_in[8];
    const float* norm2_b = (const float*)d_in[9];
    const float* fc1_w   = (const float*)d_in[10];
    const float* fc1_b   = (const float*)d_in[11];
    const float* fc2_w   = (const float*)d_in[12];
    const float* fc2_b   = (const float*)d_in[13];
    float* out = (float*)d_out;

    int M = in_sizes[0] / C_DIM;   // 4096
    int Nb = 2;
    int T = M / Nb;                // 2048

    __half *p_h16, *p_qkv16, *p_att16, *p_m1h, *p_w16;
    float *p_x2;
    cudaGetSymbolAddress((void**)&p_h16,   g_h16);
    cudaGetSymbolAddress((void**)&p_qkv16, g_qkv16);
    cudaGetSymbolAddress((void**)&p_att16, g_att16);
    cudaGetSymbolAddress((void**)&p_x2,    g_x2);
    cudaGetSymbolAddress((void**)&p_m1h,   g_m1h);
    cudaGetSymbolAddress((void**)&p_w16,   g_w16);

    const int FA_SMEM  = (FA_TOK + 2 * FA_SPAN) * FA_STR * 2 + 64 * 4;
    const int HG_SMEM  = 2 * 36864;   // 73728
    const int HG64_SMEM = 2 * (9216 + 18432);  // 55296
    cudaFuncSetAttribute(fattn_kernel,
        cudaFuncAttributeMaxDynamicSharedMemorySize, FA_SMEM);
    cudaFuncSetAttribute(hgemm<false>,
        cudaFuncAttributeMaxDynamicSharedMemorySize, HG_SMEM);
    cudaFuncSetAttribute(hgemm<true>,
        cudaFuncAttributeMaxDynamicSharedMemorySize, HG_SMEM);
    cudaFuncSetAttribute(hgemm64,
        cudaFuncAttributeMaxDynamicSharedMemorySize, HG64_SMEM);

    // 0+1) fused weights->fp16 and LN1
    prep<<<6144 + M, 128>>>(qkv_w, proj_w, fc1_w, fc2_w, p_w16,
                            x, norm1_w, norm1_b, p_h16);

    // 2) qkv (fp16)
    hgemm<false><<<dim3(QKV_DIM / 128, M / 128), 256, HG_SMEM>>>(
        p_h16, p_w16 + W_QKV, qkv_b, p_qkv16, M, QKV_DIM, C_DIM);

    // 3) flash windowed attention (fp16)
    fattn_kernel<<<dim3(T / FA_TOK, 8, Nb), 256, FA_SMEM>>>(
        p_qkv16, relbias, p_att16, T);

    // 4) x2 = att @ proj_w^T + proj_b + x   (direct epilogue, fp32)
    hgemm64<<<dim3(C_DIM / 128, M / 64), 256, HG64_SMEM>>>(
        p_att16, p_w16 + W_PROJ, proj_b, x, p_x2, M, C_DIM, C_DIM);

    // 5) h = LN2(x2) -> fp16
    ln_kernel_h<<<M, 128>>>(p_x2, norm2_w, norm2_b, p_h16);

    // 6) m1 = gelu(h @ fc1_w^T + fc1_b)  (fp16)
    hgemm<true><<<dim3(HID_DIM / 128, M / 128), 256, HG_SMEM>>>(
        p_h16, p_w16 + W_FC1, fc1_b, p_m1h, M, HID_DIM, C_DIM);

    // 7) out = m1 @ fc2_w^T + fc2_b + x2  (direct epilogue, fp32)
    hgemm64<<<dim3(C_DIM / 128, M / 64), 256, HG64_SMEM>>>(
        p_m1h, p_w16 + W_FC2, fc2_b, p_x2, out, M, C_DIM, HID_DIM);
}

// round 14
// speedup vs baseline: 2.3779x; 1.0323x over previous
#include <cuda_runtime.h>
#include <cuda_fp16.h>
#include <math.h>
#include <stdint.h>

// ---------------------------------------------------------------------------
// Shapes: x (N=2, T=2048, C=512), H=8, hd=64, WIN=63, LEFT=31, hid=2048
// ---------------------------------------------------------------------------
#define C_DIM   512
#define HID_DIM 2048
#define QKV_DIM 1536
#define HEAD_D  64
#define WIN     63
#define LEFT    31
#define M_ROWS  4096

// fp16 weight buffer offsets (halves)
#define W_QKV  0
#define W_PROJ 786432
#define W_FC1  1048576
#define W_FC2  2097152
#define W_TOT  3145728

// flash-attention tiling
#define FA_TOK  128
#define FA_SPAN 192
#define FA_REAL (FA_TOK + WIN - 1)  // 190
#define FA_STR  72

// ---------------------------------------------------------------------------
// Scratch
// ---------------------------------------------------------------------------
__device__ __half g_h16  [M_ROWS * C_DIM];
__device__ __half g_qkv16[M_ROWS * QKV_DIM];
__device__ __half g_att16[M_ROWS * C_DIM];
__device__ float  g_x2   [M_ROWS * C_DIM];
__device__ __half g_m1h  [M_ROWS * HID_DIM];
__device__ __half g_w16  [W_TOT];

// ---------------------------------------------------------------------------
// PTX helpers
// ---------------------------------------------------------------------------
__device__ __forceinline__ void cp_async16_s(uint32_t s, const void* g) {
    asm volatile("cp.async.cg.shared.global [%0], [%1], 16;\n" :: "r"(s), "l"(g));
}
__device__ __forceinline__ void ldsm4(uint32_t& r0, uint32_t& r1,
                                      uint32_t& r2, uint32_t& r3, uint32_t addr) {
    asm volatile("ldmatrix.sync.aligned.m8n8.x4.shared.b16 {%0,%1,%2,%3}, [%4];"
        : "=r"(r0), "=r"(r1), "=r"(r2), "=r"(r3) : "r"(addr));
}
__device__ __forceinline__ void ldsm4t(uint32_t& r0, uint32_t& r1,
                                       uint32_t& r2, uint32_t& r3, uint32_t addr) {
    asm volatile("ldmatrix.sync.aligned.m8n8.x4.trans.shared.b16 {%0,%1,%2,%3}, [%4];"
        : "=r"(r0), "=r"(r1), "=r"(r2), "=r"(r3) : "r"(addr));
}
__device__ __forceinline__ void mma_f16(float* c, const uint32_t* a, const uint32_t* b) {
    asm volatile(
        "mma.sync.aligned.m16n8k16.row.col.f32.f16.f16.f32 "
        "{%0,%1,%2,%3}, {%4,%5,%6,%7}, {%8,%9}, {%0,%1,%2,%3};\n"
        : "+f"(c[0]), "+f"(c[1]), "+f"(c[2]), "+f"(c[3])
        : "r"(a[0]), "r"(a[1]), "r"(a[2]), "r"(a[3]), "r"(b[0]), "r"(b[1]));
}
__device__ __forceinline__ uint32_t packh2(float a, float b) {
    __half2 h = __floats2half2_rn(a, b);
    return *reinterpret_cast<uint32_t*>(&h);
}

// ---------------------------------------------------------------------------
// prep: fused weight fp32->fp16 conversion (blocks 0..6143) + LN1 (rest)
// ---------------------------------------------------------------------------
__global__ __launch_bounds__(128) void prep(
    const float* __restrict__ w0, const float* __restrict__ w1,
    const float* __restrict__ w2, const float* __restrict__ w3,
    __half* __restrict__ wout,
    const float* __restrict__ x, const float* __restrict__ lw,
    const float* __restrict__ lb, __half* __restrict__ hout)
{
    if (blockIdx.x < 6144) {
        int i = blockIdx.x * 128 + threadIdx.x;
        const float* src; int off;
        if (i < 196608)      { src = w0; off = i; }
        else if (i < 262144) { src = w1; off = i - 196608; }
        else if (i < 524288) { src = w2; off = i - 262144; }
        else                 { src = w3; off = i - 524288; }
        float4 v = ((const float4*)src)[off];
        ((__half2*)wout)[2 * i]     = __floats2half2_rn(v.x, v.y);
        ((__half2*)wout)[2 * i + 1] = __floats2half2_rn(v.z, v.w);
        return;
    }
    int row = blockIdx.x - 6144;
    int tid = threadIdx.x;
    const float4* xr = (const float4*)(x + (size_t)row * C_DIM);
    float4 v = xr[tid];
    float s  = v.x + v.y + v.z + v.w;
    float sq = v.x*v.x + v.y*v.y + v.z*v.z + v.w*v.w;
    #pragma unroll
    for (int o = 16; o > 0; o >>= 1) {
        s  += __shfl_xor_sync(0xffffffffu, s,  o);
        sq += __shfl_xor_sync(0xffffffffu, sq, o);
    }
    __shared__ float ss[4], ssq[4];
    if ((tid & 31) == 0) { ss[tid >> 5] = s; ssq[tid >> 5] = sq; }
    __syncthreads();
    s  = ss[0]  + ss[1]  + ss[2]  + ss[3];
    sq = ssq[0] + ssq[1] + ssq[2] + ssq[3];
    float mu  = s * (1.0f / C_DIM);
    float var = sq * (1.0f / C_DIM) - mu * mu;
    float inv = rsqrtf(var + 1e-5f);
    float4 wv = ((const float4*)lw)[tid];
    float4 bv = ((const float4*)lb)[tid];
    float o0 = (v.x - mu) * inv * wv.x + bv.x;
    float o1 = (v.y - mu) * inv * wv.y + bv.y;
    float o2 = (v.z - mu) * inv * wv.z + bv.z;
    float o3 = (v.w - mu) * inv * wv.w + bv.w;
    __half2* po = (__half2*)(hout + (size_t)row * C_DIM);
    po[tid * 2]     = __floats2half2_rn(o0, o1);
    po[tid * 2 + 1] = __floats2half2_rn(o2, o3);
}

// ---------------------------------------------------------------------------
// LN2: fp32 in -> fp16 out
// ---------------------------------------------------------------------------
__global__ __launch_bounds__(128) void ln_kernel_h(
    const float* __restrict__ x, const float* __restrict__ w,
    const float* __restrict__ b, __half* __restrict__ out)
{
    int row = blockIdx.x;
    int tid = threadIdx.x;
    const float4* xr = (const float4*)(x + (size_t)row * C_DIM);
    float4 v = xr[tid];
    float s  = v.x + v.y + v.z + v.w;
    float sq = v.x*v.x + v.y*v.y + v.z*v.z + v.w*v.w;
    #pragma unroll
    for (int o = 16; o > 0; o >>= 1) {
        s  += __shfl_xor_sync(0xffffffffu, s,  o);
        sq += __shfl_xor_sync(0xffffffffu, sq, o);
    }
    __shared__ float ss[4], ssq[4];
    if ((tid & 31) == 0) { ss[tid >> 5] = s; ssq[tid >> 5] = sq; }
    __syncthreads();
    s  = ss[0]  + ss[1]  + ss[2]  + ss[3];
    sq = ssq[0] + ssq[1] + ssq[2] + ssq[3];
    float mu  = s * (1.0f / C_DIM);
    float var = sq * (1.0f / C_DIM) - mu * mu;
    float inv = rsqrtf(var + 1e-5f);
    float4 wv = ((const float4*)w)[tid];
    float4 bv = ((const float4*)b)[tid];
    float o0 = (v.x - mu) * inv * wv.x + bv.x;
    float o1 = (v.y - mu) * inv * wv.y + bv.y;
    float o2 = (v.z - mu) * inv * wv.z + bv.z;
    float o3 = (v.w - mu) * inv * wv.w + bv.w;
    __half2* po = (__half2*)(out + (size_t)row * C_DIM);
    po[tid * 2]     = __floats2half2_rn(o0, o1);
    po[tid * 2 + 1] = __floats2half2_rn(o2, o3);
}

// ---------------------------------------------------------------------------
// Unified HGEMM: BM=64, BN=128, BK=64, 2-stage cp.async, (256,3).
// OUTH: fp16 output (else fp32). GELU on fp16 path. RES: +res (fp32 path).
// ---------------------------------------------------------------------------
template<bool OUTH, bool GELU, bool RES>
__global__ __launch_bounds__(256, 3) void hgemm64(
    const __half* __restrict__ A, const __half* __restrict__ B,
    const float* __restrict__ bias, const float* __restrict__ res,
    void* __restrict__ Cout, int M, int N, int K)
{
    constexpr int BM = 64, BK = 64;
    constexpr int SK = 72;
    constexpr int A_BYTES = BM * SK * 2;         // 9216
    constexpr int B_BYTES = 128 * SK * 2;        // 18432
    constexpr int STAGE_BYTES = A_BYTES + B_BYTES;
    constexpr int ROWSTEP = 16 * SK * 2;

    extern __shared__ __align__(16) __half hsm[];
    const uint32_t sbase = (uint32_t)__cvta_generic_to_shared(hsm);

    const int tid  = threadIdx.x;
    const int wid  = tid >> 5;
    const int lane = tid & 31;
    const int g    = lane >> 2;
    const int tg   = lane & 3;
    const int warp_m = wid & 1;      // 32 rows
    const int warp_n = wid >> 1;     // 32 cols

    const __half* Ab = A + (size_t)blockIdx.y * BM * K;
    const __half* Bb = B + (size_t)blockIdx.x * 128 * K;

    float acc[2][4][4];
    #pragma unroll
    for (int mt = 0; mt < 2; mt++)
        #pragma unroll
        for (int nt = 0; nt < 4; nt++)
            #pragma unroll
            for (int i = 0; i < 4; i++) acc[mt][nt][i] = 0.0f;

    const int qh = lane >> 3, rh = lane & 7;
    const uint32_t a_lane =
        (uint32_t)(((warp_m * 32 + rh + 8 * (qh & 1)) * SK + (qh >> 1) * 8) * 2);
    const uint32_t b_lane =
        (uint32_t)(((warp_n * 32 + rh + 8 * (qh & 1)) * SK + (qh >> 1) * 8) * 2)
        + A_BYTES;

    auto load_chunk = [&](int buf, int k0) {
        uint32_t base = sbase + buf * STAGE_BYTES;
        #pragma unroll
        for (int it = 0; it < 2; ++it) {
            int i = tid + it * 256;
            int r = i >> 3, seg = i & 7;
            uint32_t so = (uint32_t)(r * SK + seg * 8) * 2;
            cp_async16_s(base + so, Ab + (size_t)r * K + k0 + seg * 8);
        }
        #pragma unroll
        for (int it = 0; it < 4; ++it) {
            int i = tid + it * 256;
            int r = i >> 3, seg = i & 7;
            uint32_t so = (uint32_t)(r * SK + seg * 8) * 2;
            cp_async16_s(base + A_BYTES + so, Bb + (size_t)r * K + k0 + seg * 8);
        }
    };

    const int nch = K / BK;
    load_chunk(0, 0);
    asm volatile("cp.async.commit_group;");

    for (int c = 0; c < nch; ++c) {
        asm volatile("cp.async.wait_group 0;");
        __syncthreads();

        if (c + 1 < nch) {
            load_chunk((c + 1) & 1, (c + 1) * BK);
            asm volatile("cp.async.commit_group;");
        }

        const uint32_t st = sbase + (c & 1) * STAGE_BYTES;
        #pragma unroll
        for (int ks = 0; ks < 4; ++ks) {
            uint32_t aw[2][4], bw[4][2];
            #pragma unroll
            for (int nb = 0; nb < 2; ++nb) {
                uint32_t x0, x1, x2, x3;
                ldsm4(x0, x1, x2, x3, st + b_lane + nb * ROWSTEP + ks * 32);
                bw[nb * 2][0] = x0; bw[nb * 2 + 1][0] = x1;
                bw[nb * 2][1] = x2; bw[nb * 2 + 1][1] = x3;
            }
            #pragma unroll
            for (int mt = 0; mt < 2; ++mt)
                ldsm4(aw[mt][0], aw[mt][1], aw[mt][2], aw[mt][3],
                      st + a_lane + mt * ROWSTEP + ks * 32);
            #pragma unroll
            for (int mt = 0; mt < 2; ++mt)
                #pragma unroll
                for (int nt = 0; nt < 4; ++nt)
                    mma_f16(acc[mt][nt], aw[mt], bw[nt]);
        }
    }

    const int row_base = blockIdx.y * BM + warp_m * 32;
    const int col_base = blockIdx.x * 128 + warp_n * 32;
    #pragma unroll
    for (int mt = 0; mt < 2; ++mt) {
        #pragma unroll
        for (int nt = 0; nt < 4; ++nt) {
            int r0 = row_base + mt * 16 + g;
            int c0 = col_base + nt * 8 + 2 * tg;
            float b0 = bias[c0], b1 = bias[c0 + 1];
            #pragma unroll
            for (int hh = 0; hh < 2; ++hh) {
                int r = r0 + hh * 8;
                size_t off = (size_t)r * N + c0;
                float v0 = acc[mt][nt][hh * 2 + 0] + b0;
                float v1 = acc[mt][nt][hh * 2 + 1] + b1;
                if (RES) {
                    float2 rv = *(const float2*)(res + off);
                    v0 += rv.x; v1 += rv.y;
                }
                if (GELU) {
                    v0 = 0.5f * v0 * (1.0f + erff(v0 * 0.70710678118654752f));
                    v1 = 0.5f * v1 * (1.0f + erff(v1 * 0.70710678118654752f));
                }
                if (OUTH) {
                    *(__half2*)((__half*)Cout + off) = __floats2half2_rn(v0, v1);
                } else {
                    float2 ov; ov.x = v0; ov.y = v1;
                    *(float2*)((float*)Cout + off) = ov;
                }
            }
        }
    }
}

// ---------------------------------------------------------------------------
// Flash windowed attention (R10-proven)
// ---------------------------------------------------------------------------
__global__ __launch_bounds__(256, 2) void fattn_kernel(
    const __half* __restrict__ qkv, const float* __restrict__ rel_bias,
    __half* __restrict__ out, int T)
{
    const int t0 = blockIdx.x * FA_TOK;
    const int h  = blockIdx.y;
    const int n  = blockIdx.z;
    const int tid  = threadIdx.x;
    const int wid  = tid >> 5;
    const int lane = tid & 31;
    const int g    = lane >> 2;
    const int tg   = lane & 3;

    extern __shared__ __align__(16) __half fsm[];
    __half* sQ = fsm;
    __half* sK = sQ + FA_TOK * FA_STR;
    __half* sV = sK + FA_SPAN * FA_STR;
    float*  sbias = (float*)(sV + FA_SPAN * FA_STR);
    const uint32_t sQb = (uint32_t)__cvta_generic_to_shared(sQ);
    const uint32_t sKb = (uint32_t)__cvta_generic_to_shared(sK);
    const uint32_t sVb = (uint32_t)__cvta_generic_to_shared(sV);

    if (tid < WIN) sbias[tid] = rel_bias[h * WIN + tid];
    const __half2 sc8 = __floats2half2_rn(0.125f, 0.125f);
    for (int i = tid; i < FA_TOK * 8; i += 256) {
        int j = i >> 3, seg = i & 7;
        const __half2* src = (const __half2*)(qkv +
            ((size_t)n * T + t0 + j) * QKV_DIM + h * HEAD_D + seg * 8);
        __half2* dst = (__half2*)(sQ + j * FA_STR + seg * 8);
        #pragma unroll
        for (int u = 0; u < 4; ++u) dst[u] = __hmul2(src[u], sc8);
    }
    for (int i = tid; i < FA_SPAN * 8; i += 256) {
        int j = i >> 3, seg = i & 7;
        int pos = t0 - LEFT + j;
        uint4 kv = make_uint4(0, 0, 0, 0), vv = make_uint4(0, 0, 0, 0);
        if (j < FA_REAL && pos >= 0 && pos < T) {
            const __half* base = qkv + ((size_t)n * T + pos) * QKV_DIM + h * HEAD_D;
            kv = *(const uint4*)(base + C_DIM + seg * 8);
            vv = *(const uint4*)(base + 2 * C_DIM + seg * 8);
        }
        *(uint4*)(sK + j * FA_STR + seg * 8) = kv;
        *(uint4*)(sV + j * FA_STR + seg * 8) = vv;
    }
    __syncthreads();

    const int r0 = wid * 16;
    const int qh = lane >> 3, rh = lane & 7;

    float acc[10][4];
    #pragma unroll
    for (int nt = 0; nt < 10; ++nt)
        #pragma unroll
        for (int c = 0; c < 4; ++c) acc[nt][c] = 0.0f;

    const uint32_t a_off = sQb +
        (uint32_t)(((r0 + rh + 8 * (qh & 1)) * FA_STR + (qh >> 1) * 8) * 2);
    const uint32_t b_off = sKb +
        (uint32_t)(((r0 + rh + 8 * (qh & 1)) * FA_STR + (qh >> 1) * 8) * 2);

    #pragma unroll
    for (int kc = 0; kc < 4; ++kc) {
        uint32_t aq[4];
        ldsm4(aq[0], aq[1], aq[2], aq[3], a_off + kc * 32);
        #pragma unroll
        for (int jp = 0; jp < 5; ++jp) {
            uint32_t x0, x1, x2, x3;
            ldsm4(x0, x1, x2, x3, b_off + (uint32_t)(jp * 16 * FA_STR * 2) + kc * 32);
            uint32_t bf0[2] = {x0, x2}, bf1[2] = {x1, x3};
            mma_f16(acc[jp * 2],     aq, bf0);
            mma_f16(acc[jp * 2 + 1], aq, bf1);
        }
    }

    float mx0 = -1e30f, mx1 = -1e30f;
    #pragma unroll
    for (int nt = 0; nt < 10; ++nt) {
        int jb = nt * 8 + 2 * tg;
        #pragma unroll
        for (int c = 0; c < 4; ++c) {
            int rl = g + ((c >> 1) << 3);
            int w  = jb + (c & 1) - rl;
            float s;
            if (w >= 0 && w < WIN) {
                int pos = t0 + r0 + rl - LEFT + w;
                s = acc[nt][c] + sbias[w];
                if (pos < 0 || pos >= T) s -= 100.0f;
            } else {
                s = -1e30f;
            }
            acc[nt][c] = s;
            if (c < 2) mx0 = fmaxf(mx0, s); else mx1 = fmaxf(mx1, s);
        }
    }
    mx0 = fmaxf(mx0, __shfl_xor_sync(0xffffffffu, mx0, 1));
    mx0 = fmaxf(mx0, __shfl_xor_sync(0xffffffffu, mx0, 2));
    mx1 = fmaxf(mx1, __shfl_xor_sync(0xffffffffu, mx1, 1));
    mx1 = fmaxf(mx1, __shfl_xor_sync(0xffffffffu, mx1, 2));

    float sm0 = 0.0f, sm1 = 0.0f;
    #pragma unroll
    for (int nt = 0; nt < 10; ++nt) {
        float e0 = __expf(acc[nt][0] - mx0);
        float e1 = __expf(acc[nt][1] - mx0);
        float e2 = __expf(acc[nt][2] - mx1);
        float e3 = __expf(acc[nt][3] - mx1);
        acc[nt][0] = e0; acc[nt][1] = e1; acc[nt][2] = e2; acc[nt][3] = e3;
        sm0 += e0 + e1; sm1 += e2 + e3;
    }
    sm0 += __shfl_xor_sync(0xffffffffu, sm0, 1);
    sm0 += __shfl_xor_sync(0xffffffffu, sm0, 2);
    sm1 += __shfl_xor_sync(0xffffffffu, sm1, 1);
    sm1 += __shfl_xor_sync(0xffffffffu, sm1, 2);
    const float rinv0 = 1.0f / sm0;
    const float rinv1 = 1.0f / sm1;

    float oacc[8][4];
    #pragma unroll
    for (int nt = 0; nt < 8; ++nt)
        #pragma unroll
        for (int c = 0; c < 4; ++c) oacc[nt][c] = 0.0f;

    const uint32_t v_off = sVb +
        (uint32_t)(((r0 + (lane & 15)) * FA_STR + 8 * (lane >> 4)) * 2);

    #pragma unroll
    for (int kc = 0; kc < 5; ++kc) {
        uint32_t ap[4];
        ap[0] = packh2(acc[2 * kc][0],     acc[2 * kc][1]);
        ap[1] = packh2(acc[2 * kc][2],     acc[2 * kc][3]);
        ap[2] = packh2(acc[2 * kc + 1][0], acc[2 * kc + 1][1]);
        ap[3] = packh2(acc[2 * kc + 1][2], acc[2 * kc + 1][3]);
        #pragma unroll
        for (int np = 0; np < 4; ++np) {
            uint32_t x0, x1, x2, x3;
            ldsm4t(x0, x1, x2, x3,
                   v_off + (uint32_t)(kc * 16 * FA_STR * 2) + (uint32_t)(np * 32));
            uint32_t bf0[2] = {x0, x1}, bf1[2] = {x2, x3};
            mma_f16(oacc[np * 2],     ap, bf0);
            mma_f16(oacc[np * 2 + 1], ap, bf1);
        }
    }

    __half* orow0 = out + ((size_t)n * T + t0 + r0 + g) * C_DIM + h * HEAD_D;
    __half* orow1 = orow0 + 8 * C_DIM;
    #pragma unroll
    for (int nt = 0; nt < 8; ++nt) {
        int d = nt * 8 + 2 * tg;
        *(__half2*)(orow0 + d) =
            __floats2half2_rn(oacc[nt][0] * rinv0, oacc[nt][1] * rinv0);
        *(__half2*)(orow1 + d) =
            __floats2half2_rn(oacc[nt][2] * rinv1, oacc[nt][3] * rinv1);
    }
}

// ---------------------------------------------------------------------------
// Launch
// ---------------------------------------------------------------------------
extern "C" void kernel_launch(void* const* d_in, const int* in_sizes, int n_in,
                              void* d_out, int out_size)
{
    const float* x       = (const float*)d_in[0];
    const float* norm1_w = (const float*)d_in[1];
    const float* norm1_b = (const float*)d_in[2];
    const float* qkv_w   = (const float*)d_in[3];
    const float* qkv_b   = (const float*)d_in[4];
    const float* relbias = (const float*)d_in[5];
    const float* proj_w  = (const float*)d_in[6];
    const float* proj_b  = (const float*)d_in[7];
    const float* norm2_w = (const float*)d_in[8];
    const float* norm2_b = (const float*)d_in[9];
    const float* fc1_w   = (const float*)d_in[10];
    const float* fc1_b   = (const float*)d_in[11];
    const float* fc2_w   = (const float*)d_in[12];
    const float* fc2_b   = (const float*)d_in[13];
    float* out = (float*)d_out;

    int M = in_sizes[0] / C_DIM;   // 4096
    int Nb = 2;
    int T = M / Nb;                // 2048

    __half *p_h16, *p_qkv16, *p_att16, *p_m1h, *p_w16;
    float *p_x2;
    cudaGetSymbolAddress((void**)&p_h16,   g_h16);
    cudaGetSymbolAddress((void**)&p_qkv16, g_qkv16);
    cudaGetSymbolAddress((void**)&p_att16, g_att16);
    cudaGetSymbolAddress((void**)&p_x2,    g_x2);
    cudaGetSymbolAddress((void**)&p_m1h,   g_m1h);
    cudaGetSymbolAddress((void**)&p_w16,   g_w16);

    const int FA_SMEM   = (FA_TOK + 2 * FA_SPAN) * FA_STR * 2 + 64 * 4;
    const int HG64_SMEM = 2 * (9216 + 18432);  // 55296
    cudaFuncSetAttribute(fattn_kernel,
        cudaFuncAttributeMaxDynamicSharedMemorySize, FA_SMEM);
    cudaFuncSetAttribute(hgemm64<true, false, false>,
        cudaFuncAttributeMaxDynamicSharedMemorySize, HG64_SMEM);
    cudaFuncSetAttribute(hgemm64<true, true, false>,
        cudaFuncAttributeMaxDynamicSharedMemorySize, HG64_SMEM);
    cudaFuncSetAttribute(hgemm64<false, false, true>,
        cudaFuncAttributeMaxDynamicSharedMemorySize, HG64_SMEM);

    // 0+1) fused weights->fp16 and LN1
    prep<<<6144 + M, 128>>>(qkv_w, proj_w, fc1_w, fc2_w, p_w16,
                            x, norm1_w, norm1_b, p_h16);

    // 2) qkv = h @ qkv_w^T + qkv_b  (fp16)       grid 12 x 64 = 768
    hgemm64<true, false, false><<<dim3(QKV_DIM / 128, M / 64), 256, HG64_SMEM>>>(
        p_h16, p_w16 + W_QKV, qkv_b, nullptr, p_qkv16, M, QKV_DIM, C_DIM);

    // 3) flash windowed attention (fp16)
    fattn_kernel<<<dim3(T / FA_TOK, 8, Nb), 256, FA_SMEM>>>(
        p_qkv16, relbias, p_att16, T);

    // 4) x2 = att @ proj_w^T + proj_b + x  (fp32)  grid 4 x 64 = 256
    hgemm64<false, false, true><<<dim3(C_DIM / 128, M / 64), 256, HG64_SMEM>>>(
        p_att16, p_w16 + W_PROJ, proj_b, x, p_x2, M, C_DIM, C_DIM);

    // 5) h = LN2(x2) -> fp16
    ln_kernel_h<<<M, 128>>>(p_x2, norm2_w, norm2_b, p_h16);

    // 6) m1 = gelu(h @ fc1_w^T + fc1_b)  (fp16)   grid 16 x 64 = 1024
    hgemm64<true, true, false><<<dim3(HID_DIM / 128, M / 64), 256, HG64_SMEM>>>(
        p_h16, p_w16 + W_FC1, fc1_b, nullptr, p_m1h, M, HID_DIM, C_DIM);

    // 7) out = m1 @ fc2_w^T + fc2_b + x2  (fp32)  grid 4 x 64 = 256
    hgemm64<false, false, true><<<dim3(C_DIM / 128, M / 64), 256, HG64_SMEM>>>(
        p_m1h, p_w16 + W_FC2, fc2_b, p_x2, out, M, C_DIM, HID_DIM);
}